// round 5
// baseline (speedup 1.0000x reference)
#include <cuda_runtime.h>
#include <cuda_bf16.h>
#include <math.h>

#define T_STEPS 512
#define BATCH   64
#define IDIM    1024
#define HDIM    1024
#define G4      4096
#define MTOT    (T_STEPS * BATCH)

typedef unsigned long long ull;

__device__ float g_xg[(size_t)G4 * MTOT];
__device__ float g_htr[2][(size_t)HDIM * BATCH];   // h transposed [j][b], double buffer
__device__ unsigned g_ctr;

__device__ __forceinline__ unsigned smem_u32(const void* p) {
    return (unsigned)__cvta_generic_to_shared(p);
}

// =====================================================================
// Kernel 1: x_gates GEMM via mma.sync bf16 hi/lo split (known-good R3)
// =====================================================================
#define XSP   40
#define XREG  (128 * XSP * 2)
#define XBUF  (4 * XREG)
#define XSMEM (2 * XBUF)

#define LDM4(R0, R1, R2, R3, ADDR)                                           \
    asm volatile("ldmatrix.sync.aligned.m8n8.x4.shared.b16 {%0,%1,%2,%3},[%4];" \
                 : "=r"(R0), "=r"(R1), "=r"(R2), "=r"(R3) : "r"(ADDR))
#define MMA_BF16(D, A0, A1, A2, A3, B0, B1)                                  \
    asm volatile("mma.sync.aligned.m16n8k16.row.col.f32.bf16.bf16.f32 "      \
                 "{%0,%1,%2,%3},{%4,%5,%6,%7},{%8,%9},{%0,%1,%2,%3};"        \
                 : "+f"(D[0]), "+f"(D[1]), "+f"(D[2]), "+f"(D[3])            \
                 : "r"(A0), "r"(A1), "r"(A2), "r"(A3), "r"(B0), "r"(B1))

__device__ __forceinline__ unsigned pack_bf2(float a, float b) {
    __nv_bfloat162 t = __floats2bfloat162_rn(a, b);
    return *(unsigned*)&t;
}
__device__ __forceinline__ void split_store4(unsigned ahi, unsigned alo, float4 v) {
    float h0 = __bfloat162float(__float2bfloat16_rn(v.x));
    float h1 = __bfloat162float(__float2bfloat16_rn(v.y));
    float h2 = __bfloat162float(__float2bfloat16_rn(v.z));
    float h3 = __bfloat162float(__float2bfloat16_rn(v.w));
    unsigned p01 = pack_bf2(v.x, v.y), p23 = pack_bf2(v.z, v.w);
    unsigned l01 = pack_bf2(v.x - h0, v.y - h1), l23 = pack_bf2(v.z - h2, v.w - h3);
    asm volatile("st.shared.v2.u32 [%0], {%1,%2};" :: "r"(ahi), "r"(p01), "r"(p23));
    asm volatile("st.shared.v2.u32 [%0], {%1,%2};" :: "r"(alo), "r"(l01), "r"(l23));
}

__global__ void __launch_bounds__(256, 1) xgates_mma_kernel(
    const float* __restrict__ Wih, const float* __restrict__ inp,
    const float* __restrict__ bih, const float* __restrict__ bhh)
{
    extern __shared__ char xsm[];
    const unsigned sb = smem_u32(xsm);
    const int tid = threadIdx.x, lane = tid & 31, wid = tid >> 5;
    const int n0 = blockIdx.y * 128, m0 = blockIdx.x * 128;
    const int wn = (wid & 1) * 64, wm = (wid >> 1) * 32;

    float acc[4][4][4];
#pragma unroll
    for (int f = 0; f < 4; ++f)
#pragma unroll
        for (int q = 0; q < 4; ++q)
#pragma unroll
            for (int r = 0; r < 4; ++r) acc[f][q][r] = 0.f;

    unsigned offA[4], offB[2];
    {
        const int ar = wn + (lane & 15), ac = (lane >> 4) << 3;
#pragma unroll
        for (int f = 0; f < 4; ++f) offA[f] = (unsigned)(((ar + f * 16) * XSP + ac) * 2);
        const int br = wm + (lane & 7) + ((lane >> 4) << 3);
        const int bc = ((lane >> 3) & 1) << 3;
#pragma unroll
        for (int Q = 0; Q < 2; ++Q) offB[Q] = (unsigned)(((br + Q * 16) * XSP + bc) * 2);
    }

    float4 wreg[4], xreg[4];

#define LDG_CHUNK(C)                                                          \
    {   const float* Wp = Wih + (size_t)n0 * IDIM + (C) * 32;                 \
        const float* Xp = inp + (size_t)m0 * IDIM + (C) * 32;                 \
        _Pragma("unroll")                                                     \
        for (int i = 0; i < 4; ++i) {                                         \
            int idx = tid + i * 256, row = idx >> 3, g = idx & 7;             \
            wreg[i] = *(const float4*)(Wp + (size_t)row * IDIM + g * 4);      \
            xreg[i] = *(const float4*)(Xp + (size_t)row * IDIM + g * 4);      \
        } }

#define CVT_STS(BUF)                                                          \
    {   unsigned base = sb + (BUF) * XBUF;                                    \
        _Pragma("unroll")                                                     \
        for (int i = 0; i < 4; ++i) {                                         \
            int idx = tid + i * 256, row = idx >> 3, g = idx & 7;             \
            unsigned off = (unsigned)((row * XSP + g * 4) * 2);               \
            split_store4(base + off, base + XREG + off, wreg[i]);             \
            split_store4(base + 2 * XREG + off, base + 3 * XREG + off, xreg[i]); \
        } }

#define COMPUTE(BUF)                                                          \
    {   unsigned base = sb + (BUF) * XBUF;                                    \
        _Pragma("unroll")                                                     \
        for (int kk = 0; kk < 32; kk += 16) {                                 \
            unsigned kb = kk * 2;                                             \
            unsigned bh[4][2], bl[4][2];                                      \
            _Pragma("unroll")                                                 \
            for (int Q = 0; Q < 2; ++Q) {                                     \
                unsigned r0, r1, r2, r3;                                      \
                LDM4(r0, r1, r2, r3, base + 2 * XREG + offB[Q] + kb);         \
                bh[Q*2][0] = r0; bh[Q*2][1] = r1;                             \
                bh[Q*2+1][0] = r2; bh[Q*2+1][1] = r3;                         \
                LDM4(r0, r1, r2, r3, base + 3 * XREG + offB[Q] + kb);         \
                bl[Q*2][0] = r0; bl[Q*2][1] = r1;                             \
                bl[Q*2+1][0] = r2; bl[Q*2+1][1] = r3;                         \
            }                                                                 \
            _Pragma("unroll")                                                 \
            for (int f = 0; f < 4; ++f) {                                     \
                unsigned a0, a1, a2, a3, c0, c1, c2, c3;                      \
                LDM4(a0, a1, a2, a3, base + offA[f] + kb);                    \
                LDM4(c0, c1, c2, c3, base + XREG + offA[f] + kb);             \
                _Pragma("unroll")                                             \
                for (int q = 0; q < 4; ++q) {                                 \
                    MMA_BF16(acc[f][q], a0, a1, a2, a3, bh[q][0], bh[q][1]);  \
                    MMA_BF16(acc[f][q], a0, a1, a2, a3, bl[q][0], bl[q][1]);  \
                    MMA_BF16(acc[f][q], c0, c1, c2, c3, bh[q][0], bh[q][1]);  \
                } } } }

    LDG_CHUNK(0); CVT_STS(0); __syncthreads();
    for (int c = 0; c < 32; ++c) {
        if (c < 31) LDG_CHUNK(c + 1);
        COMPUTE(c & 1);
        __syncthreads();
        if (c < 31) CVT_STS((c + 1) & 1);
        __syncthreads();
    }

    const int erow = lane >> 2, ecol = (lane & 3) * 2;
#pragma unroll
    for (int f = 0; f < 4; ++f) {
        const int n = n0 + wn + f * 16 + erow;
        const float b0 = bih[n] + bhh[n];
        const float b8 = bih[n + 8] + bhh[n + 8];
#pragma unroll
        for (int q = 0; q < 4; ++q) {
            const int m = m0 + wm + q * 8 + ecol;
            *(float2*)(g_xg + (size_t)n * MTOT + m) =
                make_float2(acc[f][q][0] + b0, acc[f][q][1] + b0);
            *(float2*)(g_xg + (size_t)(n + 8) * MTOT + m) =
                make_float2(acc[f][q][2] + b8, acc[f][q][3] + b8);
        }
    }
#undef LDG_CHUNK
#undef CVT_STS
#undef COMPUTE
}

// =====================================================================
// init: reset barrier counter + transpose h0 into g_htr[0]
// =====================================================================
__global__ void init_kernel(const float* __restrict__ h0) {
    if (blockIdx.x == 0 && threadIdx.x == 0) g_ctr = 0u;
    const int idx = blockIdx.x * 256 + threadIdx.x;   // 65536
    const int j = idx >> 6, b = idx & 63;
    g_htr[0][(size_t)j * 64 + b] = h0[(size_t)b * HDIM + j];
}

// =====================================================================
// Kernel 2: recurrent, f32x2 packed math, cp.async h-chunk pipeline
// thread = 1 gate-row x 8 batches; 128 CTAs persistent
// =====================================================================
#define GC 128
#define KC 128
#define GPAD 66
#define SM_WS 0
#define SM_HT (32 * 1024)
#define SM_GS (SM_HT + 2 * KC * 64)
#define SM_CS (SM_GS + 32 * GPAD)
#define SM_RS (SM_CS + 512)
#define SMEM_R ((SM_RS + 8) * 4)

__device__ __forceinline__ void ffma2(ull& d, ull a, ull b) {
    asm("fma.rn.f32x2 %0, %1, %2, %0;" : "+l"(d) : "l"(a), "l"(b));
}
__device__ __forceinline__ ull dup2(float w) {
    ull r; asm("mov.b64 %0, {%1,%1};" : "=l"(r) : "r"(__float_as_uint(w)));
    return r;
}
__device__ __forceinline__ float lo32(ull v) { return __uint_as_float((unsigned)v); }
__device__ __forceinline__ float hi32(ull v) { return __uint_as_float((unsigned)(v >> 32)); }
__device__ __forceinline__ float sigf(float x) { return 1.f / (1.f + expf(-x)); }
__device__ __forceinline__ void cp16(unsigned dst, const void* src) {
    asm volatile("cp.async.ca.shared.global [%0], [%1], 16;" :: "r"(dst), "l"(src));
}

__global__ void __launch_bounds__(256, 1) recurrent_kernel(
    const float* __restrict__ c0, const float* __restrict__ whh,
    const float* __restrict__ retr, float* __restrict__ out)
{
    extern __shared__ float sm[];
    float* Ws = sm + SM_WS;
    float* Gs = sm + SM_GS;
    float* Cs = sm + SM_CS;
    float* Rs = sm + SM_RS;
    const unsigned htb = smem_u32(sm + SM_HT);

    const int tid = threadIdx.x;
    const int j0 = blockIdx.x * 8;

    // stage W rows: smem row r = g*8+u <-> whh row g*1024 + j0+u
    for (int idx = tid; idx < 32 * 256; idx += 256) {
        const int r = idx >> 8, kq = (idx & 255) << 2;
        const int g = r >> 3, u = r & 7;
        *(float4*)(Ws + r * 1024 + kq) =
            *(const float4*)(whh + (size_t)(g * HDIM + j0 + u) * HDIM + kq);
    }
    if (tid < 8) Rs[tid] = retr[j0 + tid];
    for (int idx = tid; idx < 512; idx += 256) {
        const int u = idx & 7, b = idx >> 3;
        Cs[u * 64 + b] = c0[(size_t)b * HDIM + j0 + u];
    }
    __syncthreads();

    const int row = tid >> 3;          // 0..31 gate row
    const int oct = tid & 7;           // batches 8*oct .. 8*oct+7
    const float* wrow = Ws + row * 1024;
    const unsigned hoct = htb + (unsigned)(oct * 32);

    float* hT_out = out + (size_t)T_STEPS * BATCH * HDIM;
    float* cT_out = hT_out + (size_t)BATCH * HDIM;

    for (int t = 0; t < T_STEPS; ++t) {
        const float* hsrc = g_htr[t & 1];
        float* hdst = g_htr[(t + 1) & 1];

#define ISSUE(C, BUF)                                                        \
        {   const float* s = hsrc + (size_t)(C) * KC * 64;                   \
            unsigned d = htb + (BUF) * 32768u;                               \
            _Pragma("unroll")                                                \
            for (int i = 0; i < 8; ++i) {                                    \
                int u16 = tid + i * 256;                                     \
                cp16(d + (unsigned)u16 * 16, s + u16 * 4);                   \
            }                                                                \
            asm volatile("cp.async.commit_group;" ::: "memory");             \
        }
        ISSUE(0, 0); ISSUE(1, 1);

        ull a0 = 0, a1 = 0, a2 = 0, a3 = 0;

        for (int c = 0; c < HDIM / KC; ++c) {
            if (c < HDIM / KC - 1)
                asm volatile("cp.async.wait_group 1;" ::: "memory");
            else
                asm volatile("cp.async.wait_group 0;" ::: "memory");
            __syncthreads();

            const unsigned hb = hoct + (unsigned)((c & 1) * 32768);
            const float* wc = wrow + c * KC;
#pragma unroll 4
            for (int kb = 0; kb < KC; kb += 4) {
                const float4 w4 = *(const float4*)(wc + kb);
#pragma unroll
                for (int j = 0; j < 4; ++j) {
                    const ull wd = dup2(((const float*)&w4)[j]);
                    ull h01, h23, h45, h67;
                    const unsigned ad = hb + (unsigned)((kb + j) * 256);
                    asm("ld.shared.v2.b64 {%0,%1}, [%2];" : "=l"(h01), "=l"(h23) : "r"(ad));
                    asm("ld.shared.v2.b64 {%0,%1}, [%2];" : "=l"(h45), "=l"(h67) : "r"(ad + 16));
                    ffma2(a0, wd, h01); ffma2(a1, wd, h23);
                    ffma2(a2, wd, h45); ffma2(a3, wd, h67);
                }
            }
            __syncthreads();
            if (c + 2 < HDIM / KC) ISSUE(c + 2, c & 1);
        }
#undef ISSUE

        // stage gates
        float* gr = Gs + row * GPAD + oct * 8;
        *(float2*)(gr)     = make_float2(lo32(a0), hi32(a0));
        *(float2*)(gr + 2) = make_float2(lo32(a1), hi32(a1));
        *(float2*)(gr + 4) = make_float2(lo32(a2), hi32(a2));
        *(float2*)(gr + 6) = make_float2(lo32(a3), hi32(a3));
        __syncthreads();

        // epilogue
        float* o_t = out + (size_t)t * BATCH * HDIM;
#pragma unroll
        for (int c2 = 0; c2 < 2; ++c2) {
            const int cell = tid + c2 * 256;
            const int u = cell & 7, b = cell >> 3;
            const size_t m = (size_t)t * BATCH + b;
            const int j = j0 + u;

            const float gi = Gs[(0 * 8 + u) * GPAD + b] + g_xg[(size_t)(0 * HDIM + j) * MTOT + m];
            const float gf = Gs[(1 * 8 + u) * GPAD + b] + g_xg[(size_t)(1 * HDIM + j) * MTOT + m];
            const float gg = Gs[(2 * 8 + u) * GPAD + b] + g_xg[(size_t)(2 * HDIM + j) * MTOT + m];
            const float go = Gs[(3 * 8 + u) * GPAD + b] + g_xg[(size_t)(3 * HDIM + j) * MTOT + m];

            const float c = Cs[u * 64 + b];
            const float cy = sigf(gf) * c + sigf(gi) * tanhf(gg);
            float hy = sigf(go) * tanhf(cy);
            const float hpv = hsrc[(size_t)j * 64 + b];
            const float rv = Rs[u];
            hy = rv * hpv + (1.f - rv) * hy;

            Cs[u * 64 + b] = cy;
            o_t[(size_t)b * HDIM + j] = hy;
            hdst[(size_t)j * 64 + b] = hy;
            if (t == T_STEPS - 1) {
                hT_out[(size_t)b * HDIM + j] = hy;
                cT_out[(size_t)b * HDIM + j] = cy;
            }
        }

        __threadfence();
        __syncthreads();
        if (tid == 0) {
            atomicAdd(&g_ctr, 1u);
            const unsigned target = (unsigned)(t + 1) * GC;
            while (*(volatile unsigned*)&g_ctr < target) { }
        }
        __syncthreads();
    }
}

// =====================================================================
extern "C" void kernel_launch(void* const* d_in, const int* in_sizes, int n_in,
                              void* d_out, int out_size)
{
    const float* input_ = (const float*)d_in[0];
    const float* h0     = (const float*)d_in[1];
    const float* c0     = (const float*)d_in[2];
    const float* wih    = (const float*)d_in[3];
    const float* whh    = (const float*)d_in[4];
    const float* bih    = (const float*)d_in[5];
    const float* bhh    = (const float*)d_in[6];
    const float* retr   = (const float*)d_in[7];
    float* out = (float*)d_out;
    (void)in_sizes; (void)n_in; (void)out_size;

    cudaFuncSetAttribute(xgates_mma_kernel,
                         cudaFuncAttributeMaxDynamicSharedMemorySize, XSMEM);
    cudaFuncSetAttribute(recurrent_kernel,
                         cudaFuncAttributeMaxDynamicSharedMemorySize, SMEM_R);

    xgates_mma_kernel<<<dim3(MTOT / 128, G4 / 128), 256, XSMEM>>>(wih, input_, bih, bhh);
    init_kernel<<<256, 256>>>(h0);
    recurrent_kernel<<<GC, 256, SMEM_R>>>(c0, whh, retr, out);
}

// round 6
// speedup vs baseline: 2.2862x; 2.2862x over previous
#include <cuda_runtime.h>
#include <cuda_bf16.h>
#include <math.h>

#define T_STEPS 512
#define BATCH   64
#define IDIM    1024
#define HDIM    1024
#define G4      4096
#define MTOT    (T_STEPS * BATCH)

__device__ float g_xg[(size_t)G4 * MTOT];
__device__ unsigned g_ctr;

__device__ __forceinline__ unsigned smem_u32(const void* p) {
    return (unsigned)__cvta_generic_to_shared(p);
}

// =====================================================================
// Kernel 1: x_gates GEMM via mma.sync bf16 hi/lo split, 3-stage pipeline
// =====================================================================
#define XSP   40
#define XREG  (128 * XSP * 2)          // 10240 B
#define XBUF  (4 * XREG)               // 40960 B per stage
#define XSMEM (3 * XBUF)               // 122880 B

#define LDM4(R0, R1, R2, R3, ADDR)                                           \
    asm volatile("ldmatrix.sync.aligned.m8n8.x4.shared.b16 {%0,%1,%2,%3},[%4];" \
                 : "=r"(R0), "=r"(R1), "=r"(R2), "=r"(R3) : "r"(ADDR))
#define MMA_BF16(D, A0, A1, A2, A3, B0, B1)                                  \
    asm volatile("mma.sync.aligned.m16n8k16.row.col.f32.bf16.bf16.f32 "      \
                 "{%0,%1,%2,%3},{%4,%5,%6,%7},{%8,%9},{%0,%1,%2,%3};"        \
                 : "+f"(D[0]), "+f"(D[1]), "+f"(D[2]), "+f"(D[3])            \
                 : "r"(A0), "r"(A1), "r"(A2), "r"(A3), "r"(B0), "r"(B1))

__device__ __forceinline__ unsigned pack_bf2(float a, float b) {
    __nv_bfloat162 t = __floats2bfloat162_rn(a, b);
    return *(unsigned*)&t;
}
__device__ __forceinline__ void split_store4(unsigned ahi, unsigned alo, float4 v) {
    float h0 = __bfloat162float(__float2bfloat16_rn(v.x));
    float h1 = __bfloat162float(__float2bfloat16_rn(v.y));
    float h2 = __bfloat162float(__float2bfloat16_rn(v.z));
    float h3 = __bfloat162float(__float2bfloat16_rn(v.w));
    unsigned p01 = pack_bf2(v.x, v.y), p23 = pack_bf2(v.z, v.w);
    unsigned l01 = pack_bf2(v.x - h0, v.y - h1), l23 = pack_bf2(v.z - h2, v.w - h3);
    asm volatile("st.shared.v2.u32 [%0], {%1,%2};" :: "r"(ahi), "r"(p01), "r"(p23));
    asm volatile("st.shared.v2.u32 [%0], {%1,%2};" :: "r"(alo), "r"(l01), "r"(l23));
}

__global__ void __launch_bounds__(256, 1) xgates_mma_kernel(
    const float* __restrict__ Wih, const float* __restrict__ inp,
    const float* __restrict__ bih, const float* __restrict__ bhh)
{
    extern __shared__ char xsm[];
    const unsigned sb = smem_u32(xsm);
    const int tid = threadIdx.x, lane = tid & 31, wid = tid >> 5;
    const int n0 = blockIdx.y * 128, m0 = blockIdx.x * 128;
    const int wn = (wid & 1) * 64, wm = (wid >> 1) * 32;

    float acc[4][4][4];
#pragma unroll
    for (int f = 0; f < 4; ++f)
#pragma unroll
        for (int q = 0; q < 4; ++q)
#pragma unroll
            for (int r = 0; r < 4; ++r) acc[f][q][r] = 0.f;

    unsigned offA[4], offB[2];
    {
        const int ar = wn + (lane & 15), ac = (lane >> 4) << 3;
#pragma unroll
        for (int f = 0; f < 4; ++f) offA[f] = (unsigned)(((ar + f * 16) * XSP + ac) * 2);
        const int br = wm + (lane & 7) + ((lane >> 4) << 3);
        const int bc = ((lane >> 3) & 1) << 3;
#pragma unroll
        for (int Q = 0; Q < 2; ++Q) offB[Q] = (unsigned)(((br + Q * 16) * XSP + bc) * 2);
    }

    float4 wreg[4], xreg[4];

#define LDG_CHUNK(C)                                                          \
    {   const float* Wp = Wih + (size_t)n0 * IDIM + (C) * 32;                 \
        const float* Xp = inp + (size_t)m0 * IDIM + (C) * 32;                 \
        _Pragma("unroll")                                                     \
        for (int i = 0; i < 4; ++i) {                                         \
            int idx = tid + i * 256, row = idx >> 3, g = idx & 7;             \
            wreg[i] = *(const float4*)(Wp + (size_t)row * IDIM + g * 4);      \
            xreg[i] = *(const float4*)(Xp + (size_t)row * IDIM + g * 4);      \
        } }

#define CVT_STS(BUF)                                                          \
    {   unsigned base = sb + (BUF) * XBUF;                                    \
        _Pragma("unroll")                                                     \
        for (int i = 0; i < 4; ++i) {                                         \
            int idx = tid + i * 256, row = idx >> 3, g = idx & 7;             \
            unsigned off = (unsigned)((row * XSP + g * 4) * 2);               \
            split_store4(base + off, base + XREG + off, wreg[i]);             \
            split_store4(base + 2 * XREG + off, base + 3 * XREG + off, xreg[i]); \
        } }

#define COMPUTE(BUF)                                                          \
    {   unsigned base = sb + (BUF) * XBUF;                                    \
        _Pragma("unroll")                                                     \
        for (int kk = 0; kk < 32; kk += 16) {                                 \
            unsigned kb = kk * 2;                                             \
            unsigned bh[4][2], bl[4][2];                                      \
            _Pragma("unroll")                                                 \
            for (int Q = 0; Q < 2; ++Q) {                                     \
                unsigned r0, r1, r2, r3;                                      \
                LDM4(r0, r1, r2, r3, base + 2 * XREG + offB[Q] + kb);         \
                bh[Q*2][0] = r0; bh[Q*2][1] = r1;                             \
                bh[Q*2+1][0] = r2; bh[Q*2+1][1] = r3;                         \
                LDM4(r0, r1, r2, r3, base + 3 * XREG + offB[Q] + kb);         \
                bl[Q*2][0] = r0; bl[Q*2][1] = r1;                             \
                bl[Q*2+1][0] = r2; bl[Q*2+1][1] = r3;                         \
            }                                                                 \
            _Pragma("unroll")                                                 \
            for (int f = 0; f < 4; ++f) {                                     \
                unsigned a0, a1, a2, a3, c0, c1, c2, c3;                      \
                LDM4(a0, a1, a2, a3, base + offA[f] + kb);                    \
                LDM4(c0, c1, c2, c3, base + XREG + offA[f] + kb);             \
                _Pragma("unroll")                                             \
                for (int q = 0; q < 4; ++q) {                                 \
                    MMA_BF16(acc[f][q], a0, a1, a2, a3, bh[q][0], bh[q][1]);  \
                    MMA_BF16(acc[f][q], a0, a1, a2, a3, bl[q][0], bl[q][1]);  \
                    MMA_BF16(acc[f][q], c0, c1, c2, c3, bh[q][0], bh[q][1]);  \
                } } } }

    // prologue: fill stages 0,1
    LDG_CHUNK(0); CVT_STS(0);
    LDG_CHUNK(1); CVT_STS(1);
    __syncthreads();

    // steady state: one sync per chunk
    for (int c = 0; c < 32; ++c) {
        if (c + 2 < 32) LDG_CHUNK(c + 2);
        COMPUTE(c % 3);
        if (c + 2 < 32) CVT_STS((c + 2) % 3);
        __syncthreads();
    }

    const int erow = lane >> 2, ecol = (lane & 3) * 2;
#pragma unroll
    for (int f = 0; f < 4; ++f) {
        const int n = n0 + wn + f * 16 + erow;
        const float b0 = bih[n] + bhh[n];
        const float b8 = bih[n + 8] + bhh[n + 8];
#pragma unroll
        for (int q = 0; q < 4; ++q) {
            const int m = m0 + wm + q * 8 + ecol;
            *(float2*)(g_xg + (size_t)n * MTOT + m) =
                make_float2(acc[f][q][0] + b0, acc[f][q][1] + b0);
            *(float2*)(g_xg + (size_t)(n + 8) * MTOT + m) =
                make_float2(acc[f][q][2] + b8, acc[f][q][3] + b8);
        }
    }
#undef LDG_CHUNK
#undef CVT_STS
#undef COMPUTE
}

// =====================================================================
// Kernel 2: persistent recurrent (R1 math), double-buffered Ht,
// register prefetch, one sync per chunk
// =====================================================================
#define GC 128
#define WPAD 1025
#define HPAD 65
#define HBUF (64 * HPAD)     // 4160 floats per Ht buffer
#define GPAD 65
#define SM_WS   0
#define SM_HT   (32 * WPAD)
#define SM_GS   (SM_HT + 2 * HBUF)
#define SM_CS   (SM_GS + 32 * GPAD)
#define SM_RS   (SM_CS + 8 * 64)
#define SMEM_BYTES ((SM_RS + 8) * 4)

__global__ void reset_kernel() { g_ctr = 0u; }
__device__ __forceinline__ float sigf(float x) { return 1.f / (1.f + expf(-x)); }

__global__ void __launch_bounds__(256, 1) recurrent_kernel(
    const float* __restrict__ h0, const float* __restrict__ c0,
    const float* __restrict__ whh, const float* __restrict__ retr,
    float* __restrict__ out)
{
    extern __shared__ float sm[];
    float* Ws = sm + SM_WS;
    float* Ht = sm + SM_HT;     // 2 buffers of HBUF
    float* Gs = sm + SM_GS;
    float* Cs = sm + SM_CS;
    float* Rs = sm + SM_RS;

    const int tid = threadIdx.x;
    const int j0 = blockIdx.x * 8;

    for (int idx = tid; idx < 32 * 256; idx += 256) {
        const int r = idx >> 8, kq = (idx & 255) << 2;
        const int g = r >> 3, u = r & 7;
        const float4 v = *(const float4*)(whh + (size_t)(g * HDIM + j0 + u) * HDIM + kq);
        float* d = Ws + r * WPAD + kq;
        d[0] = v.x; d[1] = v.y; d[2] = v.z; d[3] = v.w;
    }
    if (tid < 8) Rs[tid] = retr[j0 + tid];
    for (int idx = tid; idx < 512; idx += 256) {
        const int u = idx & 7, b = idx >> 3;
        Cs[u * 64 + b] = c0[(size_t)b * HDIM + j0 + u];
    }
    __syncthreads();

    const int rg = tid >> 4, bg = tid & 15, r0 = rg * 2;
    const int ldb = tid >> 4, ldk = (tid & 15) << 2;   // h-load mapping
    float* hT_out = out + (size_t)T_STEPS * BATCH * HDIM;
    float* cT_out = hT_out + (size_t)BATCH * HDIM;

    float4 hreg[4];

#define LOADREG(HP, C)                                                       \
    {   const float* s_ = (HP) + (size_t)ldb * HDIM + (C) * 64 + ldk;        \
        hreg[0] = *(const float4*)(s_);                                      \
        hreg[1] = *(const float4*)(s_ + 16 * HDIM);                          \
        hreg[2] = *(const float4*)(s_ + 32 * HDIM);                          \
        hreg[3] = *(const float4*)(s_ + 48 * HDIM);                          \
    }
#define STOREBUF(BUF)                                                        \
    {   float* d_ = Ht + (BUF) * HBUF + ldb * HPAD + ldk;                    \
        _Pragma("unroll")                                                    \
        for (int rp = 0; rp < 4; ++rp) {                                     \
            d_[rp * 16 * HPAD + 0] = hreg[rp].x;                             \
            d_[rp * 16 * HPAD + 1] = hreg[rp].y;                             \
            d_[rp * 16 * HPAD + 2] = hreg[rp].z;                             \
            d_[rp * 16 * HPAD + 3] = hreg[rp].w;                             \
        } }

    for (int t = 0; t < T_STEPS; ++t) {
        const float* hp = (t == 0) ? h0 : (out + (size_t)(t - 1) * BATCH * HDIM);

        float acc[2][4];
#pragma unroll
        for (int a = 0; a < 2; ++a)
#pragma unroll
            for (int b = 0; b < 4; ++b) acc[a][b] = 0.f;

        LOADREG(hp, 0); STOREBUF(0);
        __syncthreads();

        for (int c = 0; c < 16; ++c) {
            if (c < 15) LOADREG(hp, c + 1);

            const float* Hb = Ht + (c & 1) * HBUF;
            const float* w0p = Ws + r0 * WPAD + c * 64;
            const float* w1p = Ws + (r0 + 1) * WPAD + c * 64;
#pragma unroll 8
            for (int k = 0; k < 64; ++k) {
                const float w0 = w0p[k], w1 = w1p[k];
                const float h0v = Hb[(bg     ) * HPAD + k];
                const float h1v = Hb[(bg + 16) * HPAD + k];
                const float h2v = Hb[(bg + 32) * HPAD + k];
                const float h3v = Hb[(bg + 48) * HPAD + k];
                acc[0][0] += w0 * h0v; acc[0][1] += w0 * h1v;
                acc[0][2] += w0 * h2v; acc[0][3] += w0 * h3v;
                acc[1][0] += w1 * h0v; acc[1][1] += w1 * h1v;
                acc[1][2] += w1 * h2v; acc[1][3] += w1 * h3v;
            }
            if (c < 15) STOREBUF((c + 1) & 1);
            __syncthreads();
        }

#pragma unroll
        for (int rr = 0; rr < 2; ++rr)
#pragma unroll
            for (int i = 0; i < 4; ++i)
                Gs[(r0 + rr) * GPAD + bg + 16 * i] = acc[rr][i];
        __syncthreads();

        float* o_t = out + (size_t)t * BATCH * HDIM;
#pragma unroll
        for (int c2 = 0; c2 < 2; ++c2) {
            const int cell = tid + c2 * 256;
            const int u = cell & 7, b = cell >> 3;
            const size_t m = (size_t)t * BATCH + b;
            const int j = j0 + u;

            const float gi = Gs[(0 * 8 + u) * GPAD + b] + g_xg[(size_t)(0 * HDIM + j) * MTOT + m];
            const float gf = Gs[(1 * 8 + u) * GPAD + b] + g_xg[(size_t)(1 * HDIM + j) * MTOT + m];
            const float gg = Gs[(2 * 8 + u) * GPAD + b] + g_xg[(size_t)(2 * HDIM + j) * MTOT + m];
            const float go = Gs[(3 * 8 + u) * GPAD + b] + g_xg[(size_t)(3 * HDIM + j) * MTOT + m];

            const float c = Cs[u * 64 + b];
            const float cy = sigf(gf) * c + sigf(gi) * tanhf(gg);
            float hy = sigf(go) * tanhf(cy);
            const float hpv = hp[(size_t)b * HDIM + j];
            const float rv = Rs[u];
            hy = rv * hpv + (1.f - rv) * hy;

            Cs[u * 64 + b] = cy;
            o_t[(size_t)b * HDIM + j] = hy;
            if (t == T_STEPS - 1) {
                hT_out[(size_t)b * HDIM + j] = hy;
                cT_out[(size_t)b * HDIM + j] = cy;
            }
        }

        __threadfence();
        __syncthreads();
        if (tid == 0) {
            atomicAdd(&g_ctr, 1u);
            const unsigned target = (unsigned)(t + 1) * GC;
            while (*(volatile unsigned*)&g_ctr < target) { }
        }
        __syncthreads();
    }
#undef LOADREG
#undef STOREBUF
}

// =====================================================================
extern "C" void kernel_launch(void* const* d_in, const int* in_sizes, int n_in,
                              void* d_out, int out_size)
{
    const float* input_ = (const float*)d_in[0];
    const float* h0     = (const float*)d_in[1];
    const float* c0     = (const float*)d_in[2];
    const float* wih    = (const float*)d_in[3];
    const float* whh    = (const float*)d_in[4];
    const float* bih    = (const float*)d_in[5];
    const float* bhh    = (const float*)d_in[6];
    const float* retr   = (const float*)d_in[7];
    float* out = (float*)d_out;
    (void)in_sizes; (void)n_in; (void)out_size;

    cudaFuncSetAttribute(xgates_mma_kernel,
                         cudaFuncAttributeMaxDynamicSharedMemorySize, XSMEM);
    cudaFuncSetAttribute(recurrent_kernel,
                         cudaFuncAttributeMaxDynamicSharedMemorySize, SMEM_BYTES);

    xgates_mma_kernel<<<dim3(MTOT / 128, G4 / 128), 256, XSMEM>>>(wih, input_, bih, bhh);
    reset_kernel<<<1, 1>>>();
    recurrent_kernel<<<GC, 256, SMEM_BYTES>>>(h0, c0, whh, retr, out);
}

// round 7
// speedup vs baseline: 2.3273x; 1.0180x over previous
#include <cuda_runtime.h>
#include <cuda_bf16.h>
#include <math.h>

#define T_STEPS 512
#define BATCH   64
#define IDIM    1024
#define HDIM    1024
#define G4      4096
#define MTOT    (T_STEPS * BATCH)

__device__ float g_xg[(size_t)G4 * MTOT];
__device__ unsigned g_ctr;
// packed bf16 hi/lo in smem-tile layout:
// per (tile,chunk): hi region 10240B then lo region 10240B (rows 80B, halves 0..31 valid)
__device__ char g_wp[(size_t)32 * 32 * 20480];    // 20 MB
__device__ char g_xp[(size_t)256 * 32 * 20480];   // 160 MB

__device__ __forceinline__ unsigned smem_u32(const void* p) {
    return (unsigned)__cvta_generic_to_shared(p);
}

// =====================================================================
// prep: fp32 -> bf16 hi/lo, tile layout. One (row,colgroup) per thread.
// =====================================================================
__global__ void __launch_bounds__(256) conv_kernel(
    const float* __restrict__ W, const float* __restrict__ X)
{
    const size_t gid = (size_t)blockIdx.x * 256 + threadIdx.x;
    const float* srcbase;
    char* dst;
    size_t pos;
    if (gid < 655360) {            // W: 1024 (nt,c) pairs x 640 units
        pos = gid;
        const size_t pair = pos / 640;
        dst = g_wp + pair * 20480;
        srcbase = W + (pair >> 5) * 128 * 1024 + (pair & 31) * 32;
    } else {                       // X: 8192 pairs x 640 units
        pos = gid - 655360;
        const size_t pair = pos / 640;
        dst = g_xp + pair * 20480;
        srcbase = X + (pair >> 5) * 128 * 1024 + (pair & 31) * 32;
    }
    const unsigned o = (unsigned)(pos % 640) * 16;   // byte offset in region
    const unsigned row = o / 80, colb = o % 80, col = colb >> 1;
    union { __nv_bfloat16 h[8]; uint4 v; } H, L;
    if (col >= 32) {
        H.v = make_uint4(0, 0, 0, 0); L.v = H.v;
    } else {
        const float* s = srcbase + (size_t)row * 1024 + col;
        float4 a = *(const float4*)s, b = *(const float4*)(s + 4);
        float f[8] = {a.x, a.y, a.z, a.w, b.x, b.y, b.z, b.w};
#pragma unroll
        for (int j = 0; j < 8; ++j) {
            __nv_bfloat16 hb = __float2bfloat16_rn(f[j]);
            H.h[j] = hb;
            L.h[j] = __float2bfloat16_rn(f[j] - __bfloat162float(hb));
        }
    }
    *(uint4*)(dst + o) = H.v;            // hi region
    *(uint4*)(dst + 10240 + o) = L.v;    // lo region
}

// =====================================================================
// Kernel 1: x_gates GEMM, mma.sync bf16 hi/lo, cp.async 4-stage pipeline
// =====================================================================
#define XSP   40
#define XREG  (128 * XSP * 2)          // 10240
#define XBUF  (4 * XREG)               // 40960 per stage
#define XSMEM (4 * XBUF)               // 163840

#define LDM4(R0, R1, R2, R3, ADDR)                                           \
    asm volatile("ldmatrix.sync.aligned.m8n8.x4.shared.b16 {%0,%1,%2,%3},[%4];" \
                 : "=r"(R0), "=r"(R1), "=r"(R2), "=r"(R3) : "r"(ADDR))
#define MMA_BF16(D, A0, A1, A2, A3, B0, B1)                                  \
    asm volatile("mma.sync.aligned.m16n8k16.row.col.f32.bf16.bf16.f32 "      \
                 "{%0,%1,%2,%3},{%4,%5,%6,%7},{%8,%9},{%0,%1,%2,%3};"        \
                 : "+f"(D[0]), "+f"(D[1]), "+f"(D[2]), "+f"(D[3])            \
                 : "r"(A0), "r"(A1), "r"(A2), "r"(A3), "r"(B0), "r"(B1))

__device__ __forceinline__ void cp16(unsigned dst, const void* src) {
    asm volatile("cp.async.ca.shared.global [%0], [%1], 16;" :: "r"(dst), "l"(src));
}

__global__ void __launch_bounds__(256, 1) xgates_mma_kernel(
    const float* __restrict__ bih, const float* __restrict__ bhh)
{
    extern __shared__ char xsm[];
    const unsigned sb = smem_u32(xsm);
    const int tid = threadIdx.x, lane = tid & 31, wid = tid >> 5;
    const size_t nt = blockIdx.y, mt = blockIdx.x;
    const int n0 = (int)nt * 128, m0 = (int)mt * 128;
    const int wn = (wid & 1) * 64, wm = (wid >> 1) * 32;

    float acc[4][4][4];
#pragma unroll
    for (int f = 0; f < 4; ++f)
#pragma unroll
        for (int q = 0; q < 4; ++q)
#pragma unroll
            for (int r = 0; r < 4; ++r) acc[f][q][r] = 0.f;

    unsigned offA[4], offB[2];
    {
        const int ar = wn + (lane & 15), ac = (lane >> 4) << 3;
#pragma unroll
        for (int f = 0; f < 4; ++f) offA[f] = (unsigned)(((ar + f * 16) * XSP + ac) * 2);
        const int br = wm + (lane & 7) + ((lane >> 4) << 3);
        const int bc = ((lane >> 3) & 1) << 3;
#pragma unroll
        for (int Q = 0; Q < 2; ++Q) offB[Q] = (unsigned)(((br + Q * 16) * XSP + bc) * 2);
    }

    const char* wbase = g_wp + nt * 32 * 20480;
    const char* xbase = g_xp + mt * 32 * 20480;

#define ISSUE(C)                                                              \
    {   const char* ws = wbase + (size_t)(C) * 20480;                         \
        const char* xs = xbase + (size_t)(C) * 20480;                         \
        unsigned d = sb + ((C) & 3) * XBUF;                                   \
        _Pragma("unroll")                                                     \
        for (int i = 0; i < 5; ++i) {                                         \
            unsigned u = (unsigned)(tid + i * 256) * 16;                      \
            cp16(d + u, ws + u);                                              \
            cp16(d + 20480 + u, xs + u);                                      \
        }                                                                     \
        asm volatile("cp.async.commit_group;" ::: "memory");                  \
    }

#define COMPUTE(BUF)                                                          \
    {   unsigned base = sb + (BUF) * XBUF;                                    \
        _Pragma("unroll")                                                     \
        for (int kk = 0; kk < 32; kk += 16) {                                 \
            unsigned kb = kk * 2;                                             \
            unsigned bh[4][2], bl[4][2];                                      \
            _Pragma("unroll")                                                 \
            for (int Q = 0; Q < 2; ++Q) {                                     \
                unsigned r0, r1, r2, r3;                                      \
                LDM4(r0, r1, r2, r3, base + 20480 + offB[Q] + kb);            \
                bh[Q*2][0] = r0; bh[Q*2][1] = r1;                             \
                bh[Q*2+1][0] = r2; bh[Q*2+1][1] = r3;                         \
                LDM4(r0, r1, r2, r3, base + 30720 + offB[Q] + kb);            \
                bl[Q*2][0] = r0; bl[Q*2][1] = r1;                             \
                bl[Q*2+1][0] = r2; bl[Q*2+1][1] = r3;                         \
            }                                                                 \
            _Pragma("unroll")                                                 \
            for (int f = 0; f < 4; ++f) {                                     \
                unsigned a0, a1, a2, a3, c0, c1, c2, c3;                      \
                LDM4(a0, a1, a2, a3, base + offA[f] + kb);                    \
                LDM4(c0, c1, c2, c3, base + 10240 + offA[f] + kb);            \
                _Pragma("unroll")                                             \
                for (int q = 0; q < 4; ++q) {                                 \
                    MMA_BF16(acc[f][q], a0, a1, a2, a3, bh[q][0], bh[q][1]);  \
                    MMA_BF16(acc[f][q], a0, a1, a2, a3, bl[q][0], bl[q][1]);  \
                    MMA_BF16(acc[f][q], c0, c1, c2, c3, bh[q][0], bh[q][1]);  \
                } } } }

    ISSUE(0); ISSUE(1); ISSUE(2);
    for (int c = 0; c < 32; ++c) {
        if (c < 30)
            asm volatile("cp.async.wait_group 2;" ::: "memory");
        else if (c == 30)
            asm volatile("cp.async.wait_group 1;" ::: "memory");
        else
            asm volatile("cp.async.wait_group 0;" ::: "memory");
        __syncthreads();
        if (c + 3 < 32) ISSUE(c + 3);
        COMPUTE(c & 3);
    }
#undef ISSUE
#undef COMPUTE

    __syncthreads();
    const int erow = lane >> 2, ecol = (lane & 3) * 2;
#pragma unroll
    for (int f = 0; f < 4; ++f) {
        const int n = n0 + wn + f * 16 + erow;
        const float b0 = bih[n] + bhh[n];
        const float b8 = bih[n + 8] + bhh[n + 8];
#pragma unroll
        for (int q = 0; q < 4; ++q) {
            const int m = m0 + wm + q * 8 + ecol;
            *(float2*)(g_xg + (size_t)n * MTOT + m) =
                make_float2(acc[f][q][0] + b0, acc[f][q][1] + b0);
            *(float2*)(g_xg + (size_t)(n + 8) * MTOT + m) =
                make_float2(acc[f][q][2] + b8, acc[f][q][3] + b8);
        }
    }
}

// =====================================================================
// Kernel 2: persistent recurrent (R6, known-good)
// =====================================================================
#define GC 128
#define WPAD 1025
#define HPAD 65
#define HBUF (64 * HPAD)
#define GPAD 65
#define SM_WS   0
#define SM_HT   (32 * WPAD)
#define SM_GS   (SM_HT + 2 * HBUF)
#define SM_CS   (SM_GS + 32 * GPAD)
#define SM_RS   (SM_CS + 8 * 64)
#define SMEM_BYTES ((SM_RS + 8) * 4)

__global__ void reset_kernel() { g_ctr = 0u; }
__device__ __forceinline__ float sigf(float x) { return 1.f / (1.f + expf(-x)); }

__global__ void __launch_bounds__(256, 1) recurrent_kernel(
    const float* __restrict__ h0, const float* __restrict__ c0,
    const float* __restrict__ whh, const float* __restrict__ retr,
    float* __restrict__ out)
{
    extern __shared__ float sm[];
    float* Ws = sm + SM_WS;
    float* Ht = sm + SM_HT;
    float* Gs = sm + SM_GS;
    float* Cs = sm + SM_CS;
    float* Rs = sm + SM_RS;

    const int tid = threadIdx.x;
    const int j0 = blockIdx.x * 8;

    for (int idx = tid; idx < 32 * 256; idx += 256) {
        const int r = idx >> 8, kq = (idx & 255) << 2;
        const int g = r >> 3, u = r & 7;
        const float4 v = *(const float4*)(whh + (size_t)(g * HDIM + j0 + u) * HDIM + kq);
        float* d = Ws + r * WPAD + kq;
        d[0] = v.x; d[1] = v.y; d[2] = v.z; d[3] = v.w;
    }
    if (tid < 8) Rs[tid] = retr[j0 + tid];
    for (int idx = tid; idx < 512; idx += 256) {
        const int u = idx & 7, b = idx >> 3;
        Cs[u * 64 + b] = c0[(size_t)b * HDIM + j0 + u];
    }
    __syncthreads();

    const int rg = tid >> 4, bg = tid & 15, r0 = rg * 2;
    const int ldb = tid >> 4, ldk = (tid & 15) << 2;
    float* hT_out = out + (size_t)T_STEPS * BATCH * HDIM;
    float* cT_out = hT_out + (size_t)BATCH * HDIM;

    float4 hreg[4];

#define LOADREG(HP, C)                                                       \
    {   const float* s_ = (HP) + (size_t)ldb * HDIM + (C) * 64 + ldk;        \
        hreg[0] = *(const float4*)(s_);                                      \
        hreg[1] = *(const float4*)(s_ + 16 * HDIM);                          \
        hreg[2] = *(const float4*)(s_ + 32 * HDIM);                          \
        hreg[3] = *(const float4*)(s_ + 48 * HDIM);                          \
    }
#define STOREBUF(BUF)                                                        \
    {   float* d_ = Ht + (BUF) * HBUF + ldb * HPAD + ldk;                    \
        _Pragma("unroll")                                                    \
        for (int rp = 0; rp < 4; ++rp) {                                     \
            d_[rp * 16 * HPAD + 0] = hreg[rp].x;                             \
            d_[rp * 16 * HPAD + 1] = hreg[rp].y;                             \
            d_[rp * 16 * HPAD + 2] = hreg[rp].z;                             \
            d_[rp * 16 * HPAD + 3] = hreg[rp].w;                             \
        } }

    for (int t = 0; t < T_STEPS; ++t) {
        const float* hp = (t == 0) ? h0 : (out + (size_t)(t - 1) * BATCH * HDIM);

        float acc[2][4];
#pragma unroll
        for (int a = 0; a < 2; ++a)
#pragma unroll
            for (int b = 0; b < 4; ++b) acc[a][b] = 0.f;

        LOADREG(hp, 0); STOREBUF(0);
        __syncthreads();

        for (int c = 0; c < 16; ++c) {
            if (c < 15) LOADREG(hp, c + 1);

            const float* Hb = Ht + (c & 1) * HBUF;
            const float* w0p = Ws + r0 * WPAD + c * 64;
            const float* w1p = Ws + (r0 + 1) * WPAD + c * 64;
#pragma unroll 8
            for (int k = 0; k < 64; ++k) {
                const float w0 = w0p[k], w1 = w1p[k];
                const float h0v = Hb[(bg     ) * HPAD + k];
                const float h1v = Hb[(bg + 16) * HPAD + k];
                const float h2v = Hb[(bg + 32) * HPAD + k];
                const float h3v = Hb[(bg + 48) * HPAD + k];
                acc[0][0] += w0 * h0v; acc[0][1] += w0 * h1v;
                acc[0][2] += w0 * h2v; acc[0][3] += w0 * h3v;
                acc[1][0] += w1 * h0v; acc[1][1] += w1 * h1v;
                acc[1][2] += w1 * h2v; acc[1][3] += w1 * h3v;
            }
            if (c < 15) STOREBUF((c + 1) & 1);
            __syncthreads();
        }

#pragma unroll
        for (int rr = 0; rr < 2; ++rr)
#pragma unroll
            for (int i = 0; i < 4; ++i)
                Gs[(r0 + rr) * GPAD + bg + 16 * i] = acc[rr][i];
        __syncthreads();

        float* o_t = out + (size_t)t * BATCH * HDIM;
#pragma unroll
        for (int c2 = 0; c2 < 2; ++c2) {
            const int cell = tid + c2 * 256;
            const int u = cell & 7, b = cell >> 3;
            const size_t m = (size_t)t * BATCH + b;
            const int j = j0 + u;

            const float gi = Gs[(0 * 8 + u) * GPAD + b] + g_xg[(size_t)(0 * HDIM + j) * MTOT + m];
            const float gf = Gs[(1 * 8 + u) * GPAD + b] + g_xg[(size_t)(1 * HDIM + j) * MTOT + m];
            const float gg = Gs[(2 * 8 + u) * GPAD + b] + g_xg[(size_t)(2 * HDIM + j) * MTOT + m];
            const float go = Gs[(3 * 8 + u) * GPAD + b] + g_xg[(size_t)(3 * HDIM + j) * MTOT + m];

            const float c = Cs[u * 64 + b];
            const float cy = sigf(gf) * c + sigf(gi) * tanhf(gg);
            float hy = sigf(go) * tanhf(cy);
            const float hpv = hp[(size_t)b * HDIM + j];
            const float rv = Rs[u];
            hy = rv * hpv + (1.f - rv) * hy;

            Cs[u * 64 + b] = cy;
            o_t[(size_t)b * HDIM + j] = hy;
            if (t == T_STEPS - 1) {
                hT_out[(size_t)b * HDIM + j] = hy;
                cT_out[(size_t)b * HDIM + j] = cy;
            }
        }

        __threadfence();
        __syncthreads();
        if (tid == 0) {
            atomicAdd(&g_ctr, 1u);
            const unsigned target = (unsigned)(t + 1) * GC;
            while (*(volatile unsigned*)&g_ctr < target) { }
        }
        __syncthreads();
    }
#undef LOADREG
#undef STOREBUF
}

// =====================================================================
extern "C" void kernel_launch(void* const* d_in, const int* in_sizes, int n_in,
                              void* d_out, int out_size)
{
    const float* input_ = (const float*)d_in[0];
    const float* h0     = (const float*)d_in[1];
    const float* c0     = (const float*)d_in[2];
    const float* wih    = (const float*)d_in[3];
    const float* whh    = (const float*)d_in[4];
    const float* bih    = (const float*)d_in[5];
    const float* bhh    = (const float*)d_in[6];
    const float* retr   = (const float*)d_in[7];
    float* out = (float*)d_out;
    (void)in_sizes; (void)n_in; (void)out_size;

    cudaFuncSetAttribute(xgates_mma_kernel,
                         cudaFuncAttributeMaxDynamicSharedMemorySize, XSMEM);
    cudaFuncSetAttribute(recurrent_kernel,
                         cudaFuncAttributeMaxDynamicSharedMemorySize, SMEM_BYTES);

    conv_kernel<<<23040, 256>>>(wih, input_);
    xgates_mma_kernel<<<dim3(256, 32), 256, XSMEM>>>(bih, bhh);
    reset_kernel<<<1, 1>>>();
    recurrent_kernel<<<GC, 256, SMEM_BYTES>>>(h0, c0, whh, retr, out);
}

// round 8
// speedup vs baseline: 4.9978x; 2.1475x over previous
#include <cuda_runtime.h>
#include <cuda_bf16.h>
#include <math.h>

#define T_STEPS 512
#define BATCH   64
#define IDIM    1024
#define HDIM    1024
#define G4      4096
#define MTOT    (T_STEPS * BATCH)

__device__ float g_xg[(size_t)G4 * MTOT];
__device__ unsigned g_ctr;
__device__ char g_wp[(size_t)32 * 32 * 20480];
__device__ char g_xp[(size_t)256 * 32 * 20480];
// h as bf16 hi/lo, [buf][hi/lo][b:64][k:1024]
__device__ __nv_bfloat16 g_hbf[2 * 2 * 64 * 1024];

__device__ __forceinline__ unsigned smem_u32(const void* p) {
    return (unsigned)__cvta_generic_to_shared(p);
}

#define LDM4(R0, R1, R2, R3, ADDR)                                           \
    asm volatile("ldmatrix.sync.aligned.m8n8.x4.shared.b16 {%0,%1,%2,%3},[%4];" \
                 : "=r"(R0), "=r"(R1), "=r"(R2), "=r"(R3) : "r"(ADDR))
#define MMA_BF16(D, A0, A1, A2, A3, B0, B1)                                  \
    asm volatile("mma.sync.aligned.m16n8k16.row.col.f32.bf16.bf16.f32 "      \
                 "{%0,%1,%2,%3},{%4,%5,%6,%7},{%8,%9},{%0,%1,%2,%3};"        \
                 : "+f"(D[0]), "+f"(D[1]), "+f"(D[2]), "+f"(D[3])            \
                 : "r"(A0), "r"(A1), "r"(A2), "r"(A3), "r"(B0), "r"(B1))

__device__ __forceinline__ void cp16(unsigned dst, const void* src) {
    asm volatile("cp.async.ca.shared.global [%0], [%1], 16;" :: "r"(dst), "l"(src));
}
__device__ __forceinline__ float sigf(float x) { return 1.f / (1.f + expf(-x)); }

// =====================================================================
// prep: fp32 -> bf16 hi/lo tiles for xgates (unchanged from R7)
// =====================================================================
__global__ void __launch_bounds__(256) conv_kernel(
    const float* __restrict__ W, const float* __restrict__ X)
{
    const size_t gid = (size_t)blockIdx.x * 256 + threadIdx.x;
    const float* srcbase;
    char* dst;
    size_t pos;
    if (gid < 655360) {
        pos = gid;
        const size_t pair = pos / 640;
        dst = g_wp + pair * 20480;
        srcbase = W + (pair >> 5) * 128 * 1024 + (pair & 31) * 32;
    } else {
        pos = gid - 655360;
        const size_t pair = pos / 640;
        dst = g_xp + pair * 20480;
        srcbase = X + (pair >> 5) * 128 * 1024 + (pair & 31) * 32;
    }
    const unsigned o = (unsigned)(pos % 640) * 16;
    const unsigned row = o / 80, colb = o % 80, col = colb >> 1;
    union { __nv_bfloat16 h[8]; uint4 v; } H, L;
    if (col >= 32) {
        H.v = make_uint4(0, 0, 0, 0); L.v = H.v;
    } else {
        const float* s = srcbase + (size_t)row * 1024 + col;
        float4 a = *(const float4*)s, b = *(const float4*)(s + 4);
        float f[8] = {a.x, a.y, a.z, a.w, b.x, b.y, b.z, b.w};
#pragma unroll
        for (int j = 0; j < 8; ++j) {
            __nv_bfloat16 hb = __float2bfloat16_rn(f[j]);
            H.h[j] = hb;
            L.h[j] = __float2bfloat16_rn(f[j] - __bfloat162float(hb));
        }
    }
    *(uint4*)(dst + o) = H.v;
    *(uint4*)(dst + 10240 + o) = L.v;
}

// =====================================================================
// Kernel 1: x_gates GEMM (unchanged from R7)
// =====================================================================
#define XSP   40
#define XREG  (128 * XSP * 2)
#define XBUF  (4 * XREG)
#define XSMEM (4 * XBUF)

__global__ void __launch_bounds__(256, 1) xgates_mma_kernel(
    const float* __restrict__ bih, const float* __restrict__ bhh)
{
    extern __shared__ char xsm[];
    const unsigned sb = smem_u32(xsm);
    const int tid = threadIdx.x, lane = tid & 31, wid = tid >> 5;
    const size_t nt = blockIdx.y, mt = blockIdx.x;
    const int n0 = (int)nt * 128, m0 = (int)mt * 128;
    const int wn = (wid & 1) * 64, wm = (wid >> 1) * 32;

    float acc[4][4][4];
#pragma unroll
    for (int f = 0; f < 4; ++f)
#pragma unroll
        for (int q = 0; q < 4; ++q)
#pragma unroll
            for (int r = 0; r < 4; ++r) acc[f][q][r] = 0.f;

    unsigned offA[4], offB[2];
    {
        const int ar = wn + (lane & 15), ac = (lane >> 4) << 3;
#pragma unroll
        for (int f = 0; f < 4; ++f) offA[f] = (unsigned)(((ar + f * 16) * XSP + ac) * 2);
        const int br = wm + (lane & 7) + ((lane >> 4) << 3);
        const int bc = ((lane >> 3) & 1) << 3;
#pragma unroll
        for (int Q = 0; Q < 2; ++Q) offB[Q] = (unsigned)(((br + Q * 16) * XSP + bc) * 2);
    }

    const char* wbase = g_wp + nt * 32 * 20480;
    const char* xbase = g_xp + mt * 32 * 20480;

#define ISSUEX(C)                                                             \
    {   const char* ws = wbase + (size_t)(C) * 20480;                         \
        const char* xs = xbase + (size_t)(C) * 20480;                         \
        unsigned d = sb + ((C) & 3) * XBUF;                                   \
        _Pragma("unroll")                                                     \
        for (int i = 0; i < 5; ++i) {                                         \
            unsigned u = (unsigned)(tid + i * 256) * 16;                      \
            cp16(d + u, ws + u);                                              \
            cp16(d + 20480 + u, xs + u);                                      \
        }                                                                     \
        asm volatile("cp.async.commit_group;" ::: "memory");                  \
    }

#define COMPUTEX(BUF)                                                         \
    {   unsigned base = sb + (BUF) * XBUF;                                    \
        _Pragma("unroll")                                                     \
        for (int kk = 0; kk < 32; kk += 16) {                                 \
            unsigned kb = kk * 2;                                             \
            unsigned bh[4][2], bl[4][2];                                      \
            _Pragma("unroll")                                                 \
            for (int Q = 0; Q < 2; ++Q) {                                     \
                unsigned r0, r1, r2, r3;                                      \
                LDM4(r0, r1, r2, r3, base + 20480 + offB[Q] + kb);            \
                bh[Q*2][0] = r0; bh[Q*2][1] = r1;                             \
                bh[Q*2+1][0] = r2; bh[Q*2+1][1] = r3;                         \
                LDM4(r0, r1, r2, r3, base + 30720 + offB[Q] + kb);            \
                bl[Q*2][0] = r0; bl[Q*2][1] = r1;                             \
                bl[Q*2+1][0] = r2; bl[Q*2+1][1] = r3;                         \
            }                                                                 \
            _Pragma("unroll")                                                 \
            for (int f = 0; f < 4; ++f) {                                     \
                unsigned a0, a1, a2, a3, c0, c1, c2, c3;                      \
                LDM4(a0, a1, a2, a3, base + offA[f] + kb);                    \
                LDM4(c0, c1, c2, c3, base + 10240 + offA[f] + kb);            \
                _Pragma("unroll")                                             \
                for (int q = 0; q < 4; ++q) {                                 \
                    MMA_BF16(acc[f][q], a0, a1, a2, a3, bh[q][0], bh[q][1]);  \
                    MMA_BF16(acc[f][q], a0, a1, a2, a3, bl[q][0], bl[q][1]);  \
                    MMA_BF16(acc[f][q], c0, c1, c2, c3, bh[q][0], bh[q][1]);  \
                } } } }

    ISSUEX(0); ISSUEX(1); ISSUEX(2);
    for (int c = 0; c < 32; ++c) {
        if (c < 30)
            asm volatile("cp.async.wait_group 2;" ::: "memory");
        else if (c == 30)
            asm volatile("cp.async.wait_group 1;" ::: "memory");
        else
            asm volatile("cp.async.wait_group 0;" ::: "memory");
        __syncthreads();
        if (c + 3 < 32) ISSUEX(c + 3);
        COMPUTEX(c & 3);
    }
#undef ISSUEX
#undef COMPUTEX

    __syncthreads();
    const int erow = lane >> 2, ecol = (lane & 3) * 2;
#pragma unroll
    for (int f = 0; f < 4; ++f) {
        const int n = n0 + wn + f * 16 + erow;
        const float b0 = bih[n] + bhh[n];
        const float b8 = bih[n + 8] + bhh[n + 8];
#pragma unroll
        for (int q = 0; q < 4; ++q) {
            const int m = m0 + wm + q * 8 + ecol;
            *(float2*)(g_xg + (size_t)n * MTOT + m) =
                make_float2(acc[f][q][0] + b0, acc[f][q][1] + b0);
            *(float2*)(g_xg + (size_t)(n + 8) * MTOT + m) =
                make_float2(acc[f][q][2] + b8, acc[f][q][3] + b8);
        }
    }
}

// =====================================================================
// init: reset barrier + convert h0 -> g_hbf buf 0
// =====================================================================
__global__ void init_kernel(const float* __restrict__ h0) {
    if (blockIdx.x == 0 && threadIdx.x == 0) g_ctr = 0u;
    const int idx = blockIdx.x * 256 + threadIdx.x;    // 65536
    const int b = idx >> 10, j = idx & 1023;
    const float v = h0[(size_t)b * HDIM + j];
    const __nv_bfloat16 hi = __float2bfloat16_rn(v);
    g_hbf[(size_t)b * 1024 + j] = hi;                          // buf0 hi
    g_hbf[65536 + (size_t)b * 1024 + j] =
        __float2bfloat16_rn(v - __bfloat162float(hi));         // buf0 lo
}

// =====================================================================
// Kernel 2: recurrent, tensor-core W_hh*h (bf16 hi/lo, 3-product)
// CTA: 32 gate rows (8 hidden units), 256 thr, 8 warps (m-tile x n16)
// =====================================================================
#define GC 128
#define WST    1032                  // halves per W smem row
#define WHI_O  0
#define WLO_O  66048
#define HT_O   132096                // 4 stages x 18432 (hi 9216 + lo 9216)
#define HSTG   18432
#define GS_O   205824                // 32 x 66 fp32
#define CS_O   214272
#define RS_O   216320
#define RSMEM  216352
#define GPAD   66

__global__ void __launch_bounds__(256, 1) recurrent_kernel(
    const float* __restrict__ h0raw, const float* __restrict__ c0,
    const float* __restrict__ whh, const float* __restrict__ retr,
    float* __restrict__ out)
{
    extern __shared__ char s[];
    const unsigned sb = smem_u32(s);
    float* Gs = (float*)(s + GS_O);
    float* Cs = (float*)(s + CS_O);
    float* Rs = (float*)(s + RS_O);

    const int tid = threadIdx.x, lane = tid & 31, wid = tid >> 5;
    const int j0 = blockIdx.x * 8;

    // convert W slice into smem hi/lo: smem row r=g*8+u <-> whh row g*1024+j0+u
    for (int idx = tid; idx < 32 * 256; idx += 256) {
        const int r = idx >> 8, kq = (idx & 255) << 2;
        const int g = r >> 3, u = r & 7;
        const float4 v = *(const float4*)(whh + (size_t)(g * HDIM + j0 + u) * HDIM + kq);
        const float f[4] = {v.x, v.y, v.z, v.w};
        __nv_bfloat16 hi[4], lo[4];
#pragma unroll
        for (int j = 0; j < 4; ++j) {
            hi[j] = __float2bfloat16_rn(f[j]);
            lo[j] = __float2bfloat16_rn(f[j] - __bfloat162float(hi[j]));
        }
        *(uint2*)(s + WHI_O + (r * WST + kq) * 2) = *(uint2*)hi;
        *(uint2*)(s + WLO_O + (r * WST + kq) * 2) = *(uint2*)lo;
    }
    if (tid < 8) Rs[tid] = retr[j0 + tid];
    for (int idx = tid; idx < 512; idx += 256) {
        const int u = idx & 7, b = idx >> 3;
        Cs[u * 64 + b] = c0[(size_t)b * HDIM + j0 + u];
    }
    __syncthreads();

    const int mtile = wid & 1;          // rows mtile*16..+15
    const int npair = wid >> 1;         // batches npair*16..+15
    const unsigned offA =
        (unsigned)(((mtile * 16 + (lane & 15)) * WST + ((lane >> 4) << 3)) * 2);
    const unsigned offB =
        (unsigned)((npair * 16 + (lane & 7) + ((lane >> 4) << 3)) * 144 +
                   ((((lane >> 3) & 1) << 3) * 2));

    float* hT_out = out + (size_t)T_STEPS * BATCH * HDIM;
    float* cT_out = hT_out + (size_t)BATCH * HDIM;

    for (int t = 0; t < T_STEPS; ++t) {
        const float* hp = (t == 0) ? h0raw : (out + (size_t)(t - 1) * BATCH * HDIM);
        const char* hsrc = (const char*)g_hbf + (size_t)(t & 1) * 262144;  // 2 planes x 128KB

#define ISSUER(C)                                                            \
        {   const unsigned dstb = sb + HT_O + ((C) & 3) * HSTG;              \
            _Pragma("unroll")                                                \
            for (int i = 0; i < 4; ++i) {                                    \
                const int u = tid + i * 256;                                 \
                const int h2 = u >> 9, v = u & 511, row = v >> 3, cg = v & 7;\
                cp16(dstb + h2 * 9216 + row * 144 + cg * 16,                 \
                     hsrc + (size_t)h2 * 131072 + row * 2048 + (C) * 128 + cg * 16); \
            }                                                                \
            asm volatile("cp.async.commit_group;" ::: "memory");             \
        }

        ISSUER(0); ISSUER(1); ISSUER(2);

        float acc0[4] = {0.f, 0.f, 0.f, 0.f};
        float acc1[4] = {0.f, 0.f, 0.f, 0.f};

        for (int c = 0; c < 16; ++c) {
            if (c <= 13)
                asm volatile("cp.async.wait_group 2;" ::: "memory");
            else if (c == 14)
                asm volatile("cp.async.wait_group 1;" ::: "memory");
            else
                asm volatile("cp.async.wait_group 0;" ::: "memory");
            __syncthreads();
            if (c + 3 < 16) ISSUER(c + 3);

            const unsigned stb = sb + HT_O + (c & 3) * HSTG;
#pragma unroll
            for (int ks = 0; ks < 4; ++ks) {
                const unsigned ka = (unsigned)((c * 64 + ks * 16) * 2);
                unsigned ah0, ah1, ah2, ah3, al0, al1, al2, al3;
                unsigned bh0, bh1, bh2, bh3, bl0, bl1, bl2, bl3;
                LDM4(ah0, ah1, ah2, ah3, sb + WHI_O + offA + ka);
                LDM4(al0, al1, al2, al3, sb + WLO_O + offA + ka);
                LDM4(bh0, bh1, bh2, bh3, stb + offB + ks * 32);
                LDM4(bl0, bl1, bl2, bl3, stb + 9216 + offB + ks * 32);
                MMA_BF16(acc0, ah0, ah1, ah2, ah3, bh0, bh1);
                MMA_BF16(acc1, ah0, ah1, ah2, ah3, bh2, bh3);
                MMA_BF16(acc0, ah0, ah1, ah2, ah3, bl0, bl1);
                MMA_BF16(acc1, ah0, ah1, ah2, ah3, bl2, bl3);
                MMA_BF16(acc0, al0, al1, al2, al3, bh0, bh1);
                MMA_BF16(acc1, al0, al1, al2, al3, bh2, bh3);
            }
        }
#undef ISSUER

        // stage gates: acc -> Gs[32][66]
        {
            const int row = mtile * 16 + (lane >> 2);
            const int col = npair * 16 + (lane & 3) * 2;
            Gs[row * GPAD + col]           = acc0[0];
            Gs[row * GPAD + col + 1]       = acc0[1];
            Gs[(row + 8) * GPAD + col]     = acc0[2];
            Gs[(row + 8) * GPAD + col + 1] = acc0[3];
            Gs[row * GPAD + col + 8]       = acc1[0];
            Gs[row * GPAD + col + 9]       = acc1[1];
            Gs[(row + 8) * GPAD + col + 8] = acc1[2];
            Gs[(row + 8) * GPAD + col + 9] = acc1[3];
        }
        __syncthreads();

        // epilogue
        float* o_t = out + (size_t)t * BATCH * HDIM;
        __nv_bfloat16* hw = g_hbf + (size_t)((t + 1) & 1) * 131072;
#pragma unroll
        for (int c2 = 0; c2 < 2; ++c2) {
            const int cell = tid + c2 * 256;
            const int u = cell & 7, b = cell >> 3;
            const size_t m = (size_t)t * BATCH + b;
            const int j = j0 + u;

            const float gi = Gs[(0 * 8 + u) * GPAD + b] + g_xg[(size_t)(0 * HDIM + j) * MTOT + m];
            const float gf = Gs[(1 * 8 + u) * GPAD + b] + g_xg[(size_t)(1 * HDIM + j) * MTOT + m];
            const float gg = Gs[(2 * 8 + u) * GPAD + b] + g_xg[(size_t)(2 * HDIM + j) * MTOT + m];
            const float go = Gs[(3 * 8 + u) * GPAD + b] + g_xg[(size_t)(3 * HDIM + j) * MTOT + m];

            const float c = Cs[u * 64 + b];
            const float cy = sigf(gf) * c + sigf(gi) * tanhf(gg);
            float hy = sigf(go) * tanhf(cy);
            const float hpv = hp[(size_t)b * HDIM + j];
            const float rv = Rs[u];
            hy = rv * hpv + (1.f - rv) * hy;

            Cs[u * 64 + b] = cy;
            o_t[(size_t)b * HDIM + j] = hy;
            const __nv_bfloat16 hhi = __float2bfloat16_rn(hy);
            hw[(size_t)b * 1024 + j] = hhi;
            hw[65536 + (size_t)b * 1024 + j] =
                __float2bfloat16_rn(hy - __bfloat162float(hhi));
            if (t == T_STEPS - 1) {
                hT_out[(size_t)b * HDIM + j] = hy;
                cT_out[(size_t)b * HDIM + j] = cy;
            }
        }

        __threadfence();
        __syncthreads();
        if (tid == 0) {
            atomicAdd(&g_ctr, 1u);
            const unsigned target = (unsigned)(t + 1) * GC;
            while (*(volatile unsigned*)&g_ctr < target) { }
        }
        __syncthreads();
    }
}

// =====================================================================
extern "C" void kernel_launch(void* const* d_in, const int* in_sizes, int n_in,
                              void* d_out, int out_size)
{
    const float* input_ = (const float*)d_in[0];
    const float* h0     = (const float*)d_in[1];
    const float* c0     = (const float*)d_in[2];
    const float* wih    = (const float*)d_in[3];
    const float* whh    = (const float*)d_in[4];
    const float* bih    = (const float*)d_in[5];
    const float* bhh    = (const float*)d_in[6];
    const float* retr   = (const float*)d_in[7];
    float* out = (float*)d_out;
    (void)in_sizes; (void)n_in; (void)out_size;

    cudaFuncSetAttribute(xgates_mma_kernel,
                         cudaFuncAttributeMaxDynamicSharedMemorySize, XSMEM);
    cudaFuncSetAttribute(recurrent_kernel,
                         cudaFuncAttributeMaxDynamicSharedMemorySize, RSMEM);

    conv_kernel<<<23040, 256>>>(wih, input_);
    xgates_mma_kernel<<<dim3(256, 32), 256, XSMEM>>>(bih, bhh);
    init_kernel<<<256, 256>>>(h0);
    recurrent_kernel<<<GC, 256, RSMEM>>>(h0, c0, whh, retr, out);
}

// round 10
// speedup vs baseline: 5.1651x; 1.0335x over previous
#include <cuda_runtime.h>
#include <cuda_bf16.h>
#include <math.h>

#define T_STEPS 512
#define BATCH   64
#define IDIM    1024
#define HDIM    1024
#define G4      4096
#define MTOT    (T_STEPS * BATCH)

__device__ float g_xg[(size_t)G4 * MTOT];
__device__ unsigned g_ctr;
__device__ char g_wp[(size_t)32 * 32 * 20480];
__device__ char g_xp[(size_t)256 * 32 * 20480];
__device__ __nv_bfloat16 g_hbf[2 * 2 * 64 * 1024];

__device__ __forceinline__ unsigned smem_u32(const void* p) {
    return (unsigned)__cvta_generic_to_shared(p);
}

#define LDM4(R0, R1, R2, R3, ADDR)                                           \
    asm volatile("ldmatrix.sync.aligned.m8n8.x4.shared.b16 {%0,%1,%2,%3},[%4];" \
                 : "=r"(R0), "=r"(R1), "=r"(R2), "=r"(R3) : "r"(ADDR))
#define MMA_BF16(D, A0, A1, A2, A3, B0, B1)                                  \
    asm volatile("mma.sync.aligned.m16n8k16.row.col.f32.bf16.bf16.f32 "      \
                 "{%0,%1,%2,%3},{%4,%5,%6,%7},{%8,%9},{%0,%1,%2,%3};"        \
                 : "+f"(D[0]), "+f"(D[1]), "+f"(D[2]), "+f"(D[3])            \
                 : "r"(A0), "r"(A1), "r"(A2), "r"(A3), "r"(B0), "r"(B1))

__device__ __forceinline__ void cp16(unsigned dst, const void* src) {
    asm volatile("cp.async.ca.shared.global [%0], [%1], 16;" :: "r"(dst), "l"(src));
}
__device__ __forceinline__ float sigf(float x) { return 1.f / (1.f + expf(-x)); }

// =====================================================================
// prep: fp32 -> bf16 hi/lo tiles for xgates (unchanged)
// =====================================================================
__global__ void __launch_bounds__(256) conv_kernel(
    const float* __restrict__ W, const float* __restrict__ X)
{
    const size_t gid = (size_t)blockIdx.x * 256 + threadIdx.x;
    const float* srcbase;
    char* dst;
    size_t pos;
    if (gid < 655360) {
        pos = gid;
        const size_t pair = pos / 640;
        dst = g_wp + pair * 20480;
        srcbase = W + (pair >> 5) * 128 * 1024 + (pair & 31) * 32;
    } else {
        pos = gid - 655360;
        const size_t pair = pos / 640;
        dst = g_xp + pair * 20480;
        srcbase = X + (pair >> 5) * 128 * 1024 + (pair & 31) * 32;
    }
    const unsigned o = (unsigned)(pos % 640) * 16;
    const unsigned row = o / 80, colb = o % 80, col = colb >> 1;
    union { __nv_bfloat16 h[8]; uint4 v; } H, L;
    if (col >= 32) {
        H.v = make_uint4(0, 0, 0, 0); L.v = H.v;
    } else {
        const float* s = srcbase + (size_t)row * 1024 + col;
        float4 a = *(const float4*)s, b = *(const float4*)(s + 4);
        float f[8] = {a.x, a.y, a.z, a.w, b.x, b.y, b.z, b.w};
#pragma unroll
        for (int j = 0; j < 8; ++j) {
            __nv_bfloat16 hb = __float2bfloat16_rn(f[j]);
            H.h[j] = hb;
            L.h[j] = __float2bfloat16_rn(f[j] - __bfloat162float(hb));
        }
    }
    *(uint4*)(dst + o) = H.v;
    *(uint4*)(dst + 10240 + o) = L.v;
}

// =====================================================================
// Kernel 1: x_gates GEMM, 128-thread CTAs, warp tile 64x64,
// 2 stages + depth-1 prefetch (race-free), 2 CTAs/SM
// =====================================================================
#define XSP   40
#define XREG  (128 * XSP * 2)          // 10240
#define XBUF  (4 * XREG)               // 40960 per stage
#define XSMEM (2 * XBUF)               // 81920

__global__ void __launch_bounds__(128, 2) xgates_mma_kernel(
    const float* __restrict__ bih, const float* __restrict__ bhh)
{
    extern __shared__ char xsm[];
    const unsigned sb = smem_u32(xsm);
    const int tid = threadIdx.x, lane = tid & 31, wid = tid >> 5;
    const size_t nt = blockIdx.y, mt = blockIdx.x;
    const int n0 = (int)nt * 128, m0 = (int)mt * 128;
    const int wn = (wid & 1) * 64, wm = (wid >> 1) * 64;

    float acc[4][8][4];
#pragma unroll
    for (int f = 0; f < 4; ++f)
#pragma unroll
        for (int q = 0; q < 8; ++q)
#pragma unroll
            for (int r = 0; r < 4; ++r) acc[f][q][r] = 0.f;

    unsigned offA[4], offB[4];
    {
        const int ar = wn + (lane & 15), ac = (lane >> 4) << 3;
#pragma unroll
        for (int f = 0; f < 4; ++f) offA[f] = (unsigned)(((ar + f * 16) * XSP + ac) * 2);
        const int br = wm + (lane & 7) + ((lane >> 4) << 3);
        const int bc = ((lane >> 3) & 1) << 3;
#pragma unroll
        for (int Q = 0; Q < 4; ++Q) offB[Q] = (unsigned)(((br + Q * 16) * XSP + bc) * 2);
    }

    const char* wbase = g_wp + nt * 32 * 20480;
    const char* xbase = g_xp + mt * 32 * 20480;

#define ISSUEX(C)                                                             \
    {   const char* ws = wbase + (size_t)(C) * 20480;                         \
        const char* xs = xbase + (size_t)(C) * 20480;                         \
        unsigned d = sb + ((C) & 1) * XBUF;                                   \
        _Pragma("unroll")                                                     \
        for (int i = 0; i < 10; ++i) {                                        \
            unsigned u = (unsigned)(tid + i * 128) * 16;                      \
            cp16(d + u, ws + u);                                              \
            cp16(d + 20480 + u, xs + u);                                      \
        }                                                                     \
        asm volatile("cp.async.commit_group;" ::: "memory");                  \
    }

#define COMPUTEX(BUF)                                                         \
    {   unsigned base = sb + (BUF) * XBUF;                                    \
        _Pragma("unroll")                                                     \
        for (int kk = 0; kk < 32; kk += 16) {                                 \
            unsigned kb = kk * 2;                                             \
            unsigned bh[8][2], bl[8][2];                                      \
            _Pragma("unroll")                                                 \
            for (int Q = 0; Q < 4; ++Q) {                                     \
                unsigned r0, r1, r2, r3;                                      \
                LDM4(r0, r1, r2, r3, base + 20480 + offB[Q] + kb);            \
                bh[Q*2][0] = r0; bh[Q*2][1] = r1;                             \
                bh[Q*2+1][0] = r2; bh[Q*2+1][1] = r3;                         \
                LDM4(r0, r1, r2, r3, base + 30720 + offB[Q] + kb);            \
                bl[Q*2][0] = r0; bl[Q*2][1] = r1;                             \
                bl[Q*2+1][0] = r2; bl[Q*2+1][1] = r3;                         \
            }                                                                 \
            _Pragma("unroll")                                                 \
            for (int f = 0; f < 4; ++f) {                                     \
                unsigned a0, a1, a2, a3, c0, c1, c2, c3;                      \
                LDM4(a0, a1, a2, a3, base + offA[f] + kb);                    \
                LDM4(c0, c1, c2, c3, base + 10240 + offA[f] + kb);            \
                _Pragma("unroll")                                             \
                for (int q = 0; q < 8; ++q) {                                 \
                    MMA_BF16(acc[f][q], a0, a1, a2, a3, bh[q][0], bh[q][1]);  \
                    MMA_BF16(acc[f][q], a0, a1, a2, a3, bl[q][0], bl[q][1]);  \
                    MMA_BF16(acc[f][q], c0, c1, c2, c3, bh[q][0], bh[q][1]);  \
                } } } }

    // depth-1 prefetch over 2 stages: never write a buffer being read
    ISSUEX(0);
    for (int c = 0; c < 32; ++c) {
        if (c + 1 < 32) {
            ISSUEX(c + 1);
            asm volatile("cp.async.wait_group 1;" ::: "memory");   // chunk c ready
        } else {
            asm volatile("cp.async.wait_group 0;" ::: "memory");
        }
        __syncthreads();          // all writes of chunk c visible to all warps
        COMPUTEX(c & 1);
        __syncthreads();          // all reads done before buffer is rewritten
    }
#undef ISSUEX
#undef COMPUTEX

    const int erow = lane >> 2, ecol = (lane & 3) * 2;
#pragma unroll
    for (int f = 0; f < 4; ++f) {
        const int n = n0 + wn + f * 16 + erow;
        const float b0 = bih[n] + bhh[n];
        const float b8 = bih[n + 8] + bhh[n + 8];
#pragma unroll
        for (int q = 0; q < 8; ++q) {
            const int m = m0 + wm + q * 8 + ecol;
            *(float2*)(g_xg + (size_t)n * MTOT + m) =
                make_float2(acc[f][q][0] + b0, acc[f][q][1] + b0);
            *(float2*)(g_xg + (size_t)(n + 8) * MTOT + m) =
                make_float2(acc[f][q][2] + b8, acc[f][q][3] + b8);
        }
    }
}

// =====================================================================
// init: reset barrier + convert h0 -> g_hbf buf 0
// =====================================================================
__global__ void init_kernel(const float* __restrict__ h0) {
    if (blockIdx.x == 0 && threadIdx.x == 0) g_ctr = 0u;
    const int idx = blockIdx.x * 256 + threadIdx.x;
    const int b = idx >> 10, j = idx & 1023;
    const float v = h0[(size_t)b * HDIM + j];
    const __nv_bfloat16 hi = __float2bfloat16_rn(v);
    g_hbf[(size_t)b * 1024 + j] = hi;
    g_hbf[65536 + (size_t)b * 1024 + j] =
        __float2bfloat16_rn(v - __bfloat162float(hi));
}

// =====================================================================
// Kernel 2: recurrent, tensor-core (R8, known-good, unchanged)
// =====================================================================
#define GC 128
#define WST    1032
#define WHI_O  0
#define WLO_O  66048
#define HT_O   132096
#define HSTG   18432
#define GS_O   205824
#define CS_O   214272
#define RS_O   216320
#define RSMEM  216352
#define GPAD   66

__global__ void __launch_bounds__(256, 1) recurrent_kernel(
    const float* __restrict__ h0raw, const float* __restrict__ c0,
    const float* __restrict__ whh, const float* __restrict__ retr,
    float* __restrict__ out)
{
    extern __shared__ char s[];
    const unsigned sb = smem_u32(s);
    float* Gs = (float*)(s + GS_O);
    float* Cs = (float*)(s + CS_O);
    float* Rs = (float*)(s + RS_O);

    const int tid = threadIdx.x, lane = tid & 31, wid = tid >> 5;
    const int j0 = blockIdx.x * 8;

    for (int idx = tid; idx < 32 * 256; idx += 256) {
        const int r = idx >> 8, kq = (idx & 255) << 2;
        const int g = r >> 3, u = r & 7;
        const float4 v = *(const float4*)(whh + (size_t)(g * HDIM + j0 + u) * HDIM + kq);
        const float f[4] = {v.x, v.y, v.z, v.w};
        __nv_bfloat16 hi[4], lo[4];
#pragma unroll
        for (int j = 0; j < 4; ++j) {
            hi[j] = __float2bfloat16_rn(f[j]);
            lo[j] = __float2bfloat16_rn(f[j] - __bfloat162float(hi[j]));
        }
        *(uint2*)(s + WHI_O + (r * WST + kq) * 2) = *(uint2*)hi;
        *(uint2*)(s + WLO_O + (r * WST + kq) * 2) = *(uint2*)lo;
    }
    if (tid < 8) Rs[tid] = retr[j0 + tid];
    for (int idx = tid; idx < 512; idx += 256) {
        const int u = idx & 7, b = idx >> 3;
        Cs[u * 64 + b] = c0[(size_t)b * HDIM + j0 + u];
    }
    __syncthreads();

    const int mtile = wid & 1;
    const int npair = wid >> 1;
    const unsigned offA =
        (unsigned)(((mtile * 16 + (lane & 15)) * WST + ((lane >> 4) << 3)) * 2);
    const unsigned offB =
        (unsigned)((npair * 16 + (lane & 7) + ((lane >> 4) << 3)) * 144 +
                   ((((lane >> 3) & 1) << 3) * 2));

    float* hT_out = out + (size_t)T_STEPS * BATCH * HDIM;
    float* cT_out = hT_out + (size_t)BATCH * HDIM;

    for (int t = 0; t < T_STEPS; ++t) {
        const float* hp = (t == 0) ? h0raw : (out + (size_t)(t - 1) * BATCH * HDIM);
        const char* hsrc = (const char*)g_hbf + (size_t)(t & 1) * 262144;

#define ISSUER(C)                                                            \
        {   const unsigned dstb = sb + HT_O + ((C) & 3) * HSTG;              \
            _Pragma("unroll")                                                \
            for (int i = 0; i < 4; ++i) {                                    \
                const int u = tid + i * 256;                                 \
                const int h2 = u >> 9, v = u & 511, row = v >> 3, cg = v & 7;\
                cp16(dstb + h2 * 9216 + row * 144 + cg * 16,                 \
                     hsrc + (size_t)h2 * 131072 + row * 2048 + (C) * 128 + cg * 16); \
            }                                                                \
            asm volatile("cp.async.commit_group;" ::: "memory");             \
        }

        ISSUER(0); ISSUER(1); ISSUER(2);

        float acc0[4] = {0.f, 0.f, 0.f, 0.f};
        float acc1[4] = {0.f, 0.f, 0.f, 0.f};

        for (int c = 0; c < 16; ++c) {
            if (c <= 13)
                asm volatile("cp.async.wait_group 2;" ::: "memory");
            else if (c == 14)
                asm volatile("cp.async.wait_group 1;" ::: "memory");
            else
                asm volatile("cp.async.wait_group 0;" ::: "memory");
            __syncthreads();
            if (c + 3 < 16) ISSUER(c + 3);

            const unsigned stb = sb + HT_O + (c & 3) * HSTG;
#pragma unroll
            for (int ks = 0; ks < 4; ++ks) {
                const unsigned ka = (unsigned)((c * 64 + ks * 16) * 2);
                unsigned ah0, ah1, ah2, ah3, al0, al1, al2, al3;
                unsigned bh0, bh1, bh2, bh3, bl0, bl1, bl2, bl3;
                LDM4(ah0, ah1, ah2, ah3, sb + WHI_O + offA + ka);
                LDM4(al0, al1, al2, al3, sb + WLO_O + offA + ka);
                LDM4(bh0, bh1, bh2, bh3, stb + offB + ks * 32);
                LDM4(bl0, bl1, bl2, bl3, stb + 9216 + offB + ks * 32);
                MMA_BF16(acc0, ah0, ah1, ah2, ah3, bh0, bh1);
                MMA_BF16(acc1, ah0, ah1, ah2, ah3, bh2, bh3);
                MMA_BF16(acc0, ah0, ah1, ah2, ah3, bl0, bl1);
                MMA_BF16(acc1, ah0, ah1, ah2, ah3, bl2, bl3);
                MMA_BF16(acc0, al0, al1, al2, al3, bh0, bh1);
                MMA_BF16(acc1, al0, al1, al2, al3, bh2, bh3);
            }
        }
#undef ISSUER

        {
            const int row = mtile * 16 + (lane >> 2);
            const int col = npair * 16 + (lane & 3) * 2;
            Gs[row * GPAD + col]           = acc0[0];
            Gs[row * GPAD + col + 1]       = acc0[1];
            Gs[(row + 8) * GPAD + col]     = acc0[2];
            Gs[(row + 8) * GPAD + col + 1] = acc0[3];
            Gs[row * GPAD + col + 8]       = acc1[0];
            Gs[row * GPAD + col + 9]       = acc1[1];
            Gs[(row + 8) * GPAD + col + 8] = acc1[2];
            Gs[(row + 8) * GPAD + col + 9] = acc1[3];
        }
        __syncthreads();

        float* o_t = out + (size_t)t * BATCH * HDIM;
        __nv_bfloat16* hw = g_hbf + (size_t)((t + 1) & 1) * 131072;
#pragma unroll
        for (int c2 = 0; c2 < 2; ++c2) {
            const int cell = tid + c2 * 256;
            const int u = cell & 7, b = cell >> 3;
            const size_t m = (size_t)t * BATCH + b;
            const int j = j0 + u;

            const float gi = Gs[(0 * 8 + u) * GPAD + b] + g_xg[(size_t)(0 * HDIM + j) * MTOT + m];
            const float gf = Gs[(1 * 8 + u) * GPAD + b] + g_xg[(size_t)(1 * HDIM + j) * MTOT + m];
            const float gg = Gs[(2 * 8 + u) * GPAD + b] + g_xg[(size_t)(2 * HDIM + j) * MTOT + m];
            const float go = Gs[(3 * 8 + u) * GPAD + b] + g_xg[(size_t)(3 * HDIM + j) * MTOT + m];

            const float c = Cs[u * 64 + b];
            const float cy = sigf(gf) * c + sigf(gi) * tanhf(gg);
            float hy = sigf(go) * tanhf(cy);
            const float hpv = hp[(size_t)b * HDIM + j];
            const float rv = Rs[u];
            hy = rv * hpv + (1.f - rv) * hy;

            Cs[u * 64 + b] = cy;
            o_t[(size_t)b * HDIM + j] = hy;
            const __nv_bfloat16 hhi = __float2bfloat16_rn(hy);
            hw[(size_t)b * 1024 + j] = hhi;
            hw[65536 + (size_t)b * 1024 + j] =
                __float2bfloat16_rn(hy - __bfloat162float(hhi));
            if (t == T_STEPS - 1) {
                hT_out[(size_t)b * HDIM + j] = hy;
                cT_out[(size_t)b * HDIM + j] = cy;
            }
        }

        __threadfence();
        __syncthreads();
        if (tid == 0) {
            atomicAdd(&g_ctr, 1u);
            const unsigned target = (unsigned)(t + 1) * GC;
            while (*(volatile unsigned*)&g_ctr < target) { }
        }
        __syncthreads();
    }
}

// =====================================================================
extern "C" void kernel_launch(void* const* d_in, const int* in_sizes, int n_in,
                              void* d_out, int out_size)
{
    const float* input_ = (const float*)d_in[0];
    const float* h0     = (const float*)d_in[1];
    const float* c0     = (const float*)d_in[2];
    const float* wih    = (const float*)d_in[3];
    const float* whh    = (const float*)d_in[4];
    const float* bih    = (const float*)d_in[5];
    const float* bhh    = (const float*)d_in[6];
    const float* retr   = (const float*)d_in[7];
    float* out = (float*)d_out;
    (void)in_sizes; (void)n_in; (void)out_size;

    cudaFuncSetAttribute(xgates_mma_kernel,
                         cudaFuncAttributeMaxDynamicSharedMemorySize, XSMEM);
    cudaFuncSetAttribute(recurrent_kernel,
                         cudaFuncAttributeMaxDynamicSharedMemorySize, RSMEM);

    conv_kernel<<<23040, 256>>>(wih, input_);
    xgates_mma_kernel<<<dim3(256, 32), 128, XSMEM>>>(bih, bhh);
    init_kernel<<<256, 256>>>(h0);
    recurrent_kernel<<<GC, 256, RSMEM>>>(h0, c0, whh, retr, out);
}

// round 11
// speedup vs baseline: 5.5185x; 1.0684x over previous
#include <cuda_runtime.h>
#include <cuda_bf16.h>
#include <cuda_fp16.h>
#include <math.h>

#define T_STEPS 512
#define BATCH   64
#define IDIM    1024
#define HDIM    1024
#define G4      4096
#define MTOT    (T_STEPS * BATCH)

__device__ float g_xg[(size_t)G4 * MTOT];
__device__ unsigned g_ctr;
__device__ char g_wp[(size_t)32 * 32 * 20480];    // W: hi+lo fp16, tile layout
__device__ char g_xp[(size_t)256 * 32 * 10240];   // X: hi fp16 only
__device__ __nv_bfloat16 g_hbf[2 * 2 * 64 * 1024];

__device__ __forceinline__ unsigned smem_u32(const void* p) {
    return (unsigned)__cvta_generic_to_shared(p);
}

#define LDM4(R0, R1, R2, R3, ADDR)                                           \
    asm volatile("ldmatrix.sync.aligned.m8n8.x4.shared.b16 {%0,%1,%2,%3},[%4];" \
                 : "=r"(R0), "=r"(R1), "=r"(R2), "=r"(R3) : "r"(ADDR))
#define MMA_BF16(D, A0, A1, A2, A3, B0, B1)                                  \
    asm volatile("mma.sync.aligned.m16n8k16.row.col.f32.bf16.bf16.f32 "      \
                 "{%0,%1,%2,%3},{%4,%5,%6,%7},{%8,%9},{%0,%1,%2,%3};"        \
                 : "+f"(D[0]), "+f"(D[1]), "+f"(D[2]), "+f"(D[3])            \
                 : "r"(A0), "r"(A1), "r"(A2), "r"(A3), "r"(B0), "r"(B1))
#define MMA_F16(D, A0, A1, A2, A3, B0, B1)                                   \
    asm volatile("mma.sync.aligned.m16n8k16.row.col.f32.f16.f16.f32 "        \
                 "{%0,%1,%2,%3},{%4,%5,%6,%7},{%8,%9},{%0,%1,%2,%3};"        \
                 : "+f"(D[0]), "+f"(D[1]), "+f"(D[2]), "+f"(D[3])            \
                 : "r"(A0), "r"(A1), "r"(A2), "r"(A3), "r"(B0), "r"(B1))

__device__ __forceinline__ void cp16(unsigned dst, const void* src) {
    asm volatile("cp.async.ca.shared.global [%0], [%1], 16;" :: "r"(dst), "l"(src));
}
__device__ __forceinline__ float sigf(float x) { return 1.f / (1.f + expf(-x)); }

// =====================================================================
// prep: W -> fp16 hi/lo planes, X -> fp16 hi plane, tile layout
// =====================================================================
__global__ void __launch_bounds__(256) conv_kernel(
    const float* __restrict__ W, const float* __restrict__ X)
{
    const size_t gid = (size_t)blockIdx.x * 256 + threadIdx.x;
    if (gid < 655360) {                       // W path: hi + lo
        const size_t pair = gid / 640;
        char* dst = g_wp + pair * 20480;
        const float* srcbase = W + (pair >> 5) * 128 * 1024 + (pair & 31) * 32;
        const unsigned o = (unsigned)(gid % 640) * 16;
        const unsigned row = o / 80, col = (o % 80) >> 1;
        union { __half h[8]; uint4 v; } H, L;
        if (col >= 32) { H.v = make_uint4(0,0,0,0); L.v = H.v; }
        else {
            const float* s = srcbase + (size_t)row * 1024 + col;
            float4 a = *(const float4*)s, b = *(const float4*)(s + 4);
            float f[8] = {a.x, a.y, a.z, a.w, b.x, b.y, b.z, b.w};
#pragma unroll
            for (int j = 0; j < 8; ++j) {
                __half hb = __float2half_rn(f[j]);
                H.h[j] = hb;
                L.h[j] = __float2half_rn(f[j] - __half2float(hb));
            }
        }
        *(uint4*)(dst + o) = H.v;
        *(uint4*)(dst + 10240 + o) = L.v;
    } else {                                   // X path: hi only
        const size_t pos = gid - 655360;       // < 5242880
        const size_t pair = pos / 640;
        char* dst = g_xp + pair * 10240;
        const float* srcbase = X + (pair >> 5) * 128 * 1024 + (pair & 31) * 32;
        const unsigned o = (unsigned)(pos % 640) * 16;
        const unsigned row = o / 80, col = (o % 80) >> 1;
        union { __half h[8]; uint4 v; } H;
        if (col >= 32) H.v = make_uint4(0,0,0,0);
        else {
            const float* s = srcbase + (size_t)row * 1024 + col;
            float4 a = *(const float4*)s, b = *(const float4*)(s + 4);
            float f[8] = {a.x, a.y, a.z, a.w, b.x, b.y, b.z, b.w};
#pragma unroll
            for (int j = 0; j < 8; ++j) H.h[j] = __float2half_rn(f[j]);
        }
        *(uint4*)(dst + o) = H.v;
    }
}

// =====================================================================
// Kernel 1: x_gates GEMM, fp16 A-split 2-product, 128-thr CTAs,
// warp tile 64x64, 2 stages depth-1 prefetch, 2 CTAs/SM
// stage layout: Whi [0,10240) Wlo [10240,20480) X [20480,30720)
// =====================================================================
#define XSP   40
#define XSTG  30720
#define XSMEM (2 * XSTG)    // 61440

__global__ void __launch_bounds__(128, 2) xgates_mma_kernel(
    const float* __restrict__ bih, const float* __restrict__ bhh)
{
    extern __shared__ char xsm[];
    const unsigned sb = smem_u32(xsm);
    const int tid = threadIdx.x, lane = tid & 31, wid = tid >> 5;
    const size_t nt = blockIdx.y, mt = blockIdx.x;
    const int n0 = (int)nt * 128, m0 = (int)mt * 128;
    const int wn = (wid & 1) * 64, wm = (wid >> 1) * 64;

    float acc[4][8][4];
#pragma unroll
    for (int f = 0; f < 4; ++f)
#pragma unroll
        for (int q = 0; q < 8; ++q)
#pragma unroll
            for (int r = 0; r < 4; ++r) acc[f][q][r] = 0.f;

    unsigned offA[4], offB[4];
    {
        const int ar = wn + (lane & 15), ac = (lane >> 4) << 3;
#pragma unroll
        for (int f = 0; f < 4; ++f) offA[f] = (unsigned)(((ar + f * 16) * XSP + ac) * 2);
        const int br = wm + (lane & 7) + ((lane >> 4) << 3);
        const int bc = ((lane >> 3) & 1) << 3;
#pragma unroll
        for (int Q = 0; Q < 4; ++Q) offB[Q] = (unsigned)(((br + Q * 16) * XSP + bc) * 2);
    }

    const char* wbase = g_wp + nt * 32 * 20480;
    const char* xbase = g_xp + mt * 32 * 10240;

#define ISSUEX(C)                                                             \
    {   const char* ws = wbase + (size_t)(C) * 20480;                         \
        const char* xs = xbase + (size_t)(C) * 10240;                         \
        unsigned d = sb + ((C) & 1) * XSTG;                                   \
        _Pragma("unroll")                                                     \
        for (int i = 0; i < 10; ++i) {                                        \
            unsigned u = (unsigned)(tid + i * 128) * 16;                      \
            cp16(d + u, ws + u);                                              \
        }                                                                     \
        _Pragma("unroll")                                                     \
        for (int i = 0; i < 5; ++i) {                                         \
            unsigned u = (unsigned)(tid + i * 128) * 16;                      \
            cp16(d + 20480 + u, xs + u);                                      \
        }                                                                     \
        asm volatile("cp.async.commit_group;" ::: "memory");                  \
    }

#define COMPUTEX(BUF)                                                         \
    {   unsigned base = sb + (BUF) * XSTG;                                    \
        _Pragma("unroll")                                                     \
        for (int kk = 0; kk < 32; kk += 16) {                                 \
            unsigned kb = kk * 2;                                             \
            unsigned bh[8][2];                                                \
            _Pragma("unroll")                                                 \
            for (int Q = 0; Q < 4; ++Q) {                                     \
                unsigned r0, r1, r2, r3;                                      \
                LDM4(r0, r1, r2, r3, base + 20480 + offB[Q] + kb);            \
                bh[Q*2][0] = r0; bh[Q*2][1] = r1;                             \
                bh[Q*2+1][0] = r2; bh[Q*2+1][1] = r3;                         \
            }                                                                 \
            _Pragma("unroll")                                                 \
            for (int f = 0; f < 4; ++f) {                                     \
                unsigned a0, a1, a2, a3, c0, c1, c2, c3;                      \
                LDM4(a0, a1, a2, a3, base + offA[f] + kb);                    \
                LDM4(c0, c1, c2, c3, base + 10240 + offA[f] + kb);            \
                _Pragma("unroll")                                             \
                for (int q = 0; q < 8; ++q) {                                 \
                    MMA_F16(acc[f][q], a0, a1, a2, a3, bh[q][0], bh[q][1]);   \
                    MMA_F16(acc[f][q], c0, c1, c2, c3, bh[q][0], bh[q][1]);   \
                } } } }

    ISSUEX(0);
    for (int c = 0; c < 32; ++c) {
        if (c + 1 < 32) {
            ISSUEX(c + 1);
            asm volatile("cp.async.wait_group 1;" ::: "memory");
        } else {
            asm volatile("cp.async.wait_group 0;" ::: "memory");
        }
        __syncthreads();
        COMPUTEX(c & 1);
        __syncthreads();
    }
#undef ISSUEX
#undef COMPUTEX

    const int erow = lane >> 2, ecol = (lane & 3) * 2;
#pragma unroll
    for (int f = 0; f < 4; ++f) {
        const int n = n0 + wn + f * 16 + erow;
        const float b0 = bih[n] + bhh[n];
        const float b8 = bih[n + 8] + bhh[n + 8];
#pragma unroll
        for (int q = 0; q < 8; ++q) {
            const int m = m0 + wm + q * 8 + ecol;
            *(float2*)(g_xg + (size_t)n * MTOT + m) =
                make_float2(acc[f][q][0] + b0, acc[f][q][1] + b0);
            *(float2*)(g_xg + (size_t)(n + 8) * MTOT + m) =
                make_float2(acc[f][q][2] + b8, acc[f][q][3] + b8);
        }
    }
}

// =====================================================================
// init: reset barrier + convert h0 -> g_hbf buf 0
// =====================================================================
__global__ void init_kernel(const float* __restrict__ h0) {
    if (blockIdx.x == 0 && threadIdx.x == 0) g_ctr = 0u;
    const int idx = blockIdx.x * 256 + threadIdx.x;
    const int b = idx >> 10, j = idx & 1023;
    const float v = h0[(size_t)b * HDIM + j];
    const __nv_bfloat16 hi = __float2bfloat16_rn(v);
    g_hbf[(size_t)b * 1024 + j] = hi;
    g_hbf[65536 + (size_t)b * 1024 + j] =
        __float2bfloat16_rn(v - __bfloat162float(hi));
}

// =====================================================================
// Kernel 2: recurrent, tensor-core (R8, known-good, unchanged)
// =====================================================================
#define GC 128
#define WST    1032
#define WHI_O  0
#define WLO_O  66048
#define HT_O   132096
#define HSTG   18432
#define GS_O   205824
#define CS_O   214272
#define RS_O   216320
#define RSMEM  216352
#define GPAD   66

__global__ void __launch_bounds__(256, 1) recurrent_kernel(
    const float* __restrict__ h0raw, const float* __restrict__ c0,
    const float* __restrict__ whh, const float* __restrict__ retr,
    float* __restrict__ out)
{
    extern __shared__ char s[];
    const unsigned sb = smem_u32(s);
    float* Gs = (float*)(s + GS_O);
    float* Cs = (float*)(s + CS_O);
    float* Rs = (float*)(s + RS_O);

    const int tid = threadIdx.x, lane = tid & 31, wid = tid >> 5;
    const int j0 = blockIdx.x * 8;

    for (int idx = tid; idx < 32 * 256; idx += 256) {
        const int r = idx >> 8, kq = (idx & 255) << 2;
        const int g = r >> 3, u = r & 7;
        const float4 v = *(const float4*)(whh + (size_t)(g * HDIM + j0 + u) * HDIM + kq);
        const float f[4] = {v.x, v.y, v.z, v.w};
        __nv_bfloat16 hi[4], lo[4];
#pragma unroll
        for (int j = 0; j < 4; ++j) {
            hi[j] = __float2bfloat16_rn(f[j]);
            lo[j] = __float2bfloat16_rn(f[j] - __bfloat162float(hi[j]));
        }
        *(uint2*)(s + WHI_O + (r * WST + kq) * 2) = *(uint2*)hi;
        *(uint2*)(s + WLO_O + (r * WST + kq) * 2) = *(uint2*)lo;
    }
    if (tid < 8) Rs[tid] = retr[j0 + tid];
    for (int idx = tid; idx < 512; idx += 256) {
        const int u = idx & 7, b = idx >> 3;
        Cs[u * 64 + b] = c0[(size_t)b * HDIM + j0 + u];
    }
    __syncthreads();

    const int mtile = wid & 1;
    const int npair = wid >> 1;
    const unsigned offA =
        (unsigned)(((mtile * 16 + (lane & 15)) * WST + ((lane >> 4) << 3)) * 2);
    const unsigned offB =
        (unsigned)((npair * 16 + (lane & 7) + ((lane >> 4) << 3)) * 144 +
                   ((((lane >> 3) & 1) << 3) * 2));

    float* hT_out = out + (size_t)T_STEPS * BATCH * HDIM;
    float* cT_out = hT_out + (size_t)BATCH * HDIM;

    for (int t = 0; t < T_STEPS; ++t) {
        const float* hp = (t == 0) ? h0raw : (out + (size_t)(t - 1) * BATCH * HDIM);
        const char* hsrc = (const char*)g_hbf + (size_t)(t & 1) * 262144;

#define ISSUER(C)                                                            \
        {   const unsigned dstb = sb + HT_O + ((C) & 3) * HSTG;              \
            _Pragma("unroll")                                                \
            for (int i = 0; i < 4; ++i) {                                    \
                const int u = tid + i * 256;                                 \
                const int h2 = u >> 9, v = u & 511, row = v >> 3, cg = v & 7;\
                cp16(dstb + h2 * 9216 + row * 144 + cg * 16,                 \
                     hsrc + (size_t)h2 * 131072 + row * 2048 + (C) * 128 + cg * 16); \
            }                                                                \
            asm volatile("cp.async.commit_group;" ::: "memory");             \
        }

        ISSUER(0); ISSUER(1); ISSUER(2);

        float acc0[4] = {0.f, 0.f, 0.f, 0.f};
        float acc1[4] = {0.f, 0.f, 0.f, 0.f};

        for (int c = 0; c < 16; ++c) {
            if (c <= 13)
                asm volatile("cp.async.wait_group 2;" ::: "memory");
            else if (c == 14)
                asm volatile("cp.async.wait_group 1;" ::: "memory");
            else
                asm volatile("cp.async.wait_group 0;" ::: "memory");
            __syncthreads();
            if (c + 3 < 16) ISSUER(c + 3);

            const unsigned stb = sb + HT_O + (c & 3) * HSTG;
#pragma unroll
            for (int ks = 0; ks < 4; ++ks) {
                const unsigned ka = (unsigned)((c * 64 + ks * 16) * 2);
                unsigned ah0, ah1, ah2, ah3, al0, al1, al2, al3;
                unsigned bh0, bh1, bh2, bh3, bl0, bl1, bl2, bl3;
                LDM4(ah0, ah1, ah2, ah3, sb + WHI_O + offA + ka);
                LDM4(al0, al1, al2, al3, sb + WLO_O + offA + ka);
                LDM4(bh0, bh1, bh2, bh3, stb + offB + ks * 32);
                LDM4(bl0, bl1, bl2, bl3, stb + 9216 + offB + ks * 32);
                MMA_BF16(acc0, ah0, ah1, ah2, ah3, bh0, bh1);
                MMA_BF16(acc1, ah0, ah1, ah2, ah3, bh2, bh3);
                MMA_BF16(acc0, ah0, ah1, ah2, ah3, bl0, bl1);
                MMA_BF16(acc1, ah0, ah1, ah2, ah3, bl2, bl3);
                MMA_BF16(acc0, al0, al1, al2, al3, bh0, bh1);
                MMA_BF16(acc1, al0, al1, al2, al3, bh2, bh3);
            }
        }
#undef ISSUER

        {
            const int row = mtile * 16 + (lane >> 2);
            const int col = npair * 16 + (lane & 3) * 2;
            Gs[row * GPAD + col]           = acc0[0];
            Gs[row * GPAD + col + 1]       = acc0[1];
            Gs[(row + 8) * GPAD + col]     = acc0[2];
            Gs[(row + 8) * GPAD + col + 1] = acc0[3];
            Gs[row * GPAD + col + 8]       = acc1[0];
            Gs[row * GPAD + col + 9]       = acc1[1];
            Gs[(row + 8) * GPAD + col + 8] = acc1[2];
            Gs[(row + 8) * GPAD + col + 9] = acc1[3];
        }
        __syncthreads();

        float* o_t = out + (size_t)t * BATCH * HDIM;
        __nv_bfloat16* hw = g_hbf + (size_t)((t + 1) & 1) * 131072;
#pragma unroll
        for (int c2 = 0; c2 < 2; ++c2) {
            const int cell = tid + c2 * 256;
            const int u = cell & 7, b = cell >> 3;
            const size_t m = (size_t)t * BATCH + b;
            const int j = j0 + u;

            const float gi = Gs[(0 * 8 + u) * GPAD + b] + g_xg[(size_t)(0 * HDIM + j) * MTOT + m];
            const float gf = Gs[(1 * 8 + u) * GPAD + b] + g_xg[(size_t)(1 * HDIM + j) * MTOT + m];
            const float gg = Gs[(2 * 8 + u) * GPAD + b] + g_xg[(size_t)(2 * HDIM + j) * MTOT + m];
            const float go = Gs[(3 * 8 + u) * GPAD + b] + g_xg[(size_t)(3 * HDIM + j) * MTOT + m];

            const float c = Cs[u * 64 + b];
            const float cy = sigf(gf) * c + sigf(gi) * tanhf(gg);
            float hy = sigf(go) * tanhf(cy);
            const float hpv = hp[(size_t)b * HDIM + j];
            const float rv = Rs[u];
            hy = rv * hpv + (1.f - rv) * hy;

            Cs[u * 64 + b] = cy;
            o_t[(size_t)b * HDIM + j] = hy;
            const __nv_bfloat16 hhi = __float2bfloat16_rn(hy);
            hw[(size_t)b * 1024 + j] = hhi;
            hw[65536 + (size_t)b * 1024 + j] =
                __float2bfloat16_rn(hy - __bfloat162float(hhi));
            if (t == T_STEPS - 1) {
                hT_out[(size_t)b * HDIM + j] = hy;
                cT_out[(size_t)b * HDIM + j] = cy;
            }
        }

        __threadfence();
        __syncthreads();
        if (tid == 0) {
            atomicAdd(&g_ctr, 1u);
            const unsigned target = (unsigned)(t + 1) * GC;
            while (*(volatile unsigned*)&g_ctr < target) { }
        }
        __syncthreads();
    }
}

// =====================================================================
extern "C" void kernel_launch(void* const* d_in, const int* in_sizes, int n_in,
                              void* d_out, int out_size)
{
    const float* input_ = (const float*)d_in[0];
    const float* h0     = (const float*)d_in[1];
    const float* c0     = (const float*)d_in[2];
    const float* wih    = (const float*)d_in[3];
    const float* whh    = (const float*)d_in[4];
    const float* bih    = (const float*)d_in[5];
    const float* bhh    = (const float*)d_in[6];
    const float* retr   = (const float*)d_in[7];
    float* out = (float*)d_out;
    (void)in_sizes; (void)n_in; (void)out_size;

    cudaFuncSetAttribute(xgates_mma_kernel,
                         cudaFuncAttributeMaxDynamicSharedMemorySize, XSMEM);
    cudaFuncSetAttribute(recurrent_kernel,
                         cudaFuncAttributeMaxDynamicSharedMemorySize, RSMEM);

    conv_kernel<<<23040, 256>>>(wih, input_);
    xgates_mma_kernel<<<dim3(256, 32), 128, XSMEM>>>(bih, bhh);
    init_kernel<<<256, 256>>>(h0);
    recurrent_kernel<<<GC, 256, RSMEM>>>(h0, c0, whh, retr, out);
}

// round 12
// speedup vs baseline: 7.1504x; 1.2957x over previous
#include <cuda_runtime.h>
#include <cuda_bf16.h>
#include <cuda_fp16.h>
#include <math.h>

#define T_STEPS 512
#define BATCH   64
#define IDIM    1024
#define HDIM    1024
#define G4      4096
#define MTOT    (T_STEPS * BATCH)

__device__ float g_xg[(size_t)G4 * MTOT];
__device__ unsigned g_ctr;
__device__ char g_wp[(size_t)32 * 32 * 20480];    // W_ih: hi+lo fp16 tiles
__device__ char g_xp[(size_t)256 * 32 * 10240];   // X: hi fp16 tiles
__device__ __half g_hf[2 * 64 * 1024];            // h fp16, double buffer

__device__ __forceinline__ unsigned smem_u32(const void* p) {
    return (unsigned)__cvta_generic_to_shared(p);
}

#define LDM4(R0, R1, R2, R3, ADDR)                                           \
    asm volatile("ldmatrix.sync.aligned.m8n8.x4.shared.b16 {%0,%1,%2,%3},[%4];" \
                 : "=r"(R0), "=r"(R1), "=r"(R2), "=r"(R3) : "r"(ADDR))
#define MMA_F16(D, A0, A1, A2, A3, B0, B1)                                   \
    asm volatile("mma.sync.aligned.m16n8k16.row.col.f32.f16.f16.f32 "        \
                 "{%0,%1,%2,%3},{%4,%5,%6,%7},{%8,%9},{%0,%1,%2,%3};"        \
                 : "+f"(D[0]), "+f"(D[1]), "+f"(D[2]), "+f"(D[3])            \
                 : "r"(A0), "r"(A1), "r"(A2), "r"(A3), "r"(B0), "r"(B1))

__device__ __forceinline__ void cp16(unsigned dst, const void* src) {
    asm volatile("cp.async.ca.shared.global [%0], [%1], 16;" :: "r"(dst), "l"(src));
}
__device__ __forceinline__ float sigf(float x) { return 1.f / (1.f + expf(-x)); }

// =====================================================================
// prep: W -> fp16 hi/lo planes, X -> fp16 hi plane, tile layout
// =====================================================================
__global__ void __launch_bounds__(256) conv_kernel(
    const float* __restrict__ W, const float* __restrict__ X)
{
    const size_t gid = (size_t)blockIdx.x * 256 + threadIdx.x;
    if (gid < 655360) {
        const size_t pair = gid / 640;
        char* dst = g_wp + pair * 20480;
        const float* srcbase = W + (pair >> 5) * 128 * 1024 + (pair & 31) * 32;
        const unsigned o = (unsigned)(gid % 640) * 16;
        const unsigned row = o / 80, col = (o % 80) >> 1;
        union { __half h[8]; uint4 v; } H, L;
        if (col >= 32) { H.v = make_uint4(0,0,0,0); L.v = H.v; }
        else {
            const float* s = srcbase + (size_t)row * 1024 + col;
            float4 a = *(const float4*)s, b = *(const float4*)(s + 4);
            float f[8] = {a.x, a.y, a.z, a.w, b.x, b.y, b.z, b.w};
#pragma unroll
            for (int j = 0; j < 8; ++j) {
                __half hb = __float2half_rn(f[j]);
                H.h[j] = hb;
                L.h[j] = __float2half_rn(f[j] - __half2float(hb));
            }
        }
        *(uint4*)(dst + o) = H.v;
        *(uint4*)(dst + 10240 + o) = L.v;
    } else {
        const size_t pos = gid - 655360;
        const size_t pair = pos / 640;
        char* dst = g_xp + pair * 10240;
        const float* srcbase = X + (pair >> 5) * 128 * 1024 + (pair & 31) * 32;
        const unsigned o = (unsigned)(pos % 640) * 16;
        const unsigned row = o / 80, col = (o % 80) >> 1;
        union { __half h[8]; uint4 v; } H;
        if (col >= 32) H.v = make_uint4(0,0,0,0);
        else {
            const float* s = srcbase + (size_t)row * 1024 + col;
            float4 a = *(const float4*)s, b = *(const float4*)(s + 4);
            float f[8] = {a.x, a.y, a.z, a.w, b.x, b.y, b.z, b.w};
#pragma unroll
            for (int j = 0; j < 8; ++j) H.h[j] = __float2half_rn(f[j]);
        }
        *(uint4*)(dst + o) = H.v;
    }
}

// =====================================================================
// Kernel 1: x_gates GEMM (R11, known-good): fp16 A-split 2-product
// =====================================================================
#define XSP   40
#define XSTG  30720
#define XSMEM (2 * XSTG)

__global__ void __launch_bounds__(128, 2) xgates_mma_kernel(
    const float* __restrict__ bih, const float* __restrict__ bhh)
{
    extern __shared__ char xsm[];
    const unsigned sb = smem_u32(xsm);
    const int tid = threadIdx.x, lane = tid & 31, wid = tid >> 5;
    const size_t nt = blockIdx.y, mt = blockIdx.x;
    const int n0 = (int)nt * 128, m0 = (int)mt * 128;
    const int wn = (wid & 1) * 64, wm = (wid >> 1) * 64;

    float acc[4][8][4];
#pragma unroll
    for (int f = 0; f < 4; ++f)
#pragma unroll
        for (int q = 0; q < 8; ++q)
#pragma unroll
            for (int r = 0; r < 4; ++r) acc[f][q][r] = 0.f;

    unsigned offA[4], offB[4];
    {
        const int ar = wn + (lane & 15), ac = (lane >> 4) << 3;
#pragma unroll
        for (int f = 0; f < 4; ++f) offA[f] = (unsigned)(((ar + f * 16) * XSP + ac) * 2);
        const int br = wm + (lane & 7) + ((lane >> 4) << 3);
        const int bc = ((lane >> 3) & 1) << 3;
#pragma unroll
        for (int Q = 0; Q < 4; ++Q) offB[Q] = (unsigned)(((br + Q * 16) * XSP + bc) * 2);
    }

    const char* wbase = g_wp + nt * 32 * 20480;
    const char* xbase = g_xp + mt * 32 * 10240;

#define ISSUEX(C)                                                             \
    {   const char* ws = wbase + (size_t)(C) * 20480;                         \
        const char* xs = xbase + (size_t)(C) * 10240;                         \
        unsigned d = sb + ((C) & 1) * XSTG;                                   \
        _Pragma("unroll")                                                     \
        for (int i = 0; i < 10; ++i) {                                        \
            unsigned u = (unsigned)(tid + i * 128) * 16;                      \
            cp16(d + u, ws + u);                                              \
        }                                                                     \
        _Pragma("unroll")                                                     \
        for (int i = 0; i < 5; ++i) {                                         \
            unsigned u = (unsigned)(tid + i * 128) * 16;                      \
            cp16(d + 20480 + u, xs + u);                                      \
        }                                                                     \
        asm volatile("cp.async.commit_group;" ::: "memory");                  \
    }

#define COMPUTEX(BUF)                                                         \
    {   unsigned base = sb + (BUF) * XSTG;                                    \
        _Pragma("unroll")                                                     \
        for (int kk = 0; kk < 32; kk += 16) {                                 \
            unsigned kb = kk * 2;                                             \
            unsigned bh[8][2];                                                \
            _Pragma("unroll")                                                 \
            for (int Q = 0; Q < 4; ++Q) {                                     \
                unsigned r0, r1, r2, r3;                                      \
                LDM4(r0, r1, r2, r3, base + 20480 + offB[Q] + kb);            \
                bh[Q*2][0] = r0; bh[Q*2][1] = r1;                             \
                bh[Q*2+1][0] = r2; bh[Q*2+1][1] = r3;                         \
            }                                                                 \
            _Pragma("unroll")                                                 \
            for (int f = 0; f < 4; ++f) {                                     \
                unsigned a0, a1, a2, a3, c0, c1, c2, c3;                      \
                LDM4(a0, a1, a2, a3, base + offA[f] + kb);                    \
                LDM4(c0, c1, c2, c3, base + 10240 + offA[f] + kb);            \
                _Pragma("unroll")                                             \
                for (int q = 0; q < 8; ++q) {                                 \
                    MMA_F16(acc[f][q], a0, a1, a2, a3, bh[q][0], bh[q][1]);   \
                    MMA_F16(acc[f][q], c0, c1, c2, c3, bh[q][0], bh[q][1]);   \
                } } } }

    ISSUEX(0);
    for (int c = 0; c < 32; ++c) {
        if (c + 1 < 32) {
            ISSUEX(c + 1);
            asm volatile("cp.async.wait_group 1;" ::: "memory");
        } else {
            asm volatile("cp.async.wait_group 0;" ::: "memory");
        }
        __syncthreads();
        COMPUTEX(c & 1);
        __syncthreads();
    }
#undef ISSUEX
#undef COMPUTEX

    const int erow = lane >> 2, ecol = (lane & 3) * 2;
#pragma unroll
    for (int f = 0; f < 4; ++f) {
        const int n = n0 + wn + f * 16 + erow;
        const float b0 = bih[n] + bhh[n];
        const float b8 = bih[n + 8] + bhh[n + 8];
#pragma unroll
        for (int q = 0; q < 8; ++q) {
            const int m = m0 + wm + q * 8 + ecol;
            *(float2*)(g_xg + (size_t)n * MTOT + m) =
                make_float2(acc[f][q][0] + b0, acc[f][q][1] + b0);
            *(float2*)(g_xg + (size_t)(n + 8) * MTOT + m) =
                make_float2(acc[f][q][2] + b8, acc[f][q][3] + b8);
        }
    }
}

// =====================================================================
// init: reset barrier + convert h0 -> g_hf buf 0 (fp16)
// =====================================================================
__global__ void init_kernel(const float* __restrict__ h0) {
    if (blockIdx.x == 0 && threadIdx.x == 0) g_ctr = 0u;
    const int idx = blockIdx.x * 256 + threadIdx.x;
    const int b = idx >> 10, j = idx & 1023;
    g_hf[(size_t)b * 1024 + j] = __float2half_rn(h0[(size_t)b * HDIM + j]);
}

// =====================================================================
// Kernel 2: recurrent, W_hh fp16 hi/lo (2-product), h fp16 single plane
// =====================================================================
#define GC 128
#define WST    1032
#define WHI_O  0
#define WLO_O  66048
#define HT_O   132096               // 4 stages x 9216
#define HSTG   9216
#define GS_O   168960               // 32 x 66 fp32
#define CS_O   177408
#define RS_O   179456
#define RSMEM  179488
#define GPAD   66

__global__ void __launch_bounds__(256, 1) recurrent_kernel(
    const float* __restrict__ h0raw, const float* __restrict__ c0,
    const float* __restrict__ whh, const float* __restrict__ retr,
    float* __restrict__ out)
{
    extern __shared__ char s[];
    const unsigned sb = smem_u32(s);
    float* Gs = (float*)(s + GS_O);
    float* Cs = (float*)(s + CS_O);
    float* Rs = (float*)(s + RS_O);

    const int tid = threadIdx.x, lane = tid & 31, wid = tid >> 5;
    const int j0 = blockIdx.x * 8;

    // convert W slice into smem fp16 hi/lo
    for (int idx = tid; idx < 32 * 256; idx += 256) {
        const int r = idx >> 8, kq = (idx & 255) << 2;
        const int g = r >> 3, u = r & 7;
        const float4 v = *(const float4*)(whh + (size_t)(g * HDIM + j0 + u) * HDIM + kq);
        const float f[4] = {v.x, v.y, v.z, v.w};
        __half hi[4], lo[4];
#pragma unroll
        for (int j = 0; j < 4; ++j) {
            hi[j] = __float2half_rn(f[j]);
            lo[j] = __float2half_rn(f[j] - __half2float(hi[j]));
        }
        *(uint2*)(s + WHI_O + (r * WST + kq) * 2) = *(uint2*)hi;
        *(uint2*)(s + WLO_O + (r * WST + kq) * 2) = *(uint2*)lo;
    }
    if (tid < 8) Rs[tid] = retr[j0 + tid];
    for (int idx = tid; idx < 512; idx += 256) {
        const int u = idx & 7, b = idx >> 3;
        Cs[u * 64 + b] = c0[(size_t)b * HDIM + j0 + u];
    }
    __syncthreads();

    const int mtile = wid & 1;
    const int npair = wid >> 1;
    const unsigned offA =
        (unsigned)(((mtile * 16 + (lane & 15)) * WST + ((lane >> 4) << 3)) * 2);
    const unsigned offB =
        (unsigned)((npair * 16 + (lane & 7) + ((lane >> 4) << 3)) * 144 +
                   ((((lane >> 3) & 1) << 3) * 2));

    float* hT_out = out + (size_t)T_STEPS * BATCH * HDIM;
    float* cT_out = hT_out + (size_t)BATCH * HDIM;

    for (int t = 0; t < T_STEPS; ++t) {
        const float* hp = (t == 0) ? h0raw : (out + (size_t)(t - 1) * BATCH * HDIM);
        const char* hsrc = (const char*)g_hf + (size_t)(t & 1) * 131072;

        // per chunk: 64 batches x 64 k fp16 = 8KB -> 512 x 16B, 2/thread
#define ISSUER(C)                                                            \
        {   const unsigned dstb = sb + HT_O + ((C) & 3) * HSTG;              \
            _Pragma("unroll")                                                \
            for (int i = 0; i < 2; ++i) {                                    \
                const int u = tid + i * 256;                                 \
                const int row = u >> 3, cg = u & 7;                          \
                cp16(dstb + row * 144 + cg * 16,                             \
                     hsrc + (size_t)row * 2048 + (C) * 128 + cg * 16);       \
            }                                                                \
            asm volatile("cp.async.commit_group;" ::: "memory");             \
        }

        ISSUER(0); ISSUER(1); ISSUER(2);

        float acc0[4] = {0.f, 0.f, 0.f, 0.f};
        float acc1[4] = {0.f, 0.f, 0.f, 0.f};

        for (int c = 0; c < 16; ++c) {
            if (c <= 13)
                asm volatile("cp.async.wait_group 2;" ::: "memory");
            else if (c == 14)
                asm volatile("cp.async.wait_group 1;" ::: "memory");
            else
                asm volatile("cp.async.wait_group 0;" ::: "memory");
            __syncthreads();
            if (c + 3 < 16) ISSUER(c + 3);

            const unsigned stb = sb + HT_O + (c & 3) * HSTG;
#pragma unroll
            for (int ks = 0; ks < 4; ++ks) {
                const unsigned ka = (unsigned)((c * 64 + ks * 16) * 2);
                unsigned ah0, ah1, ah2, ah3, al0, al1, al2, al3;
                unsigned bh0, bh1, bh2, bh3;
                LDM4(ah0, ah1, ah2, ah3, sb + WHI_O + offA + ka);
                LDM4(al0, al1, al2, al3, sb + WLO_O + offA + ka);
                LDM4(bh0, bh1, bh2, bh3, stb + offB + ks * 32);
                MMA_F16(acc0, ah0, ah1, ah2, ah3, bh0, bh1);
                MMA_F16(acc1, ah0, ah1, ah2, ah3, bh2, bh3);
                MMA_F16(acc0, al0, al1, al2, al3, bh0, bh1);
                MMA_F16(acc1, al0, al1, al2, al3, bh2, bh3);
            }
        }
#undef ISSUER

        {
            const int row = mtile * 16 + (lane >> 2);
            const int col = npair * 16 + (lane & 3) * 2;
            Gs[row * GPAD + col]           = acc0[0];
            Gs[row * GPAD + col + 1]       = acc0[1];
            Gs[(row + 8) * GPAD + col]     = acc0[2];
            Gs[(row + 8) * GPAD + col + 1] = acc0[3];
            Gs[row * GPAD + col + 8]       = acc1[0];
            Gs[row * GPAD + col + 9]       = acc1[1];
            Gs[(row + 8) * GPAD + col + 8] = acc1[2];
            Gs[(row + 8) * GPAD + col + 9] = acc1[3];
        }
        __syncthreads();

        float* o_t = out + (size_t)t * BATCH * HDIM;
        __half* hw = g_hf + (size_t)((t + 1) & 1) * 65536;
#pragma unroll
        for (int c2 = 0; c2 < 2; ++c2) {
            const int cell = tid + c2 * 256;
            const int u = cell & 7, b = cell >> 3;
            const size_t m = (size_t)t * BATCH + b;
            const int j = j0 + u;

            const float gi = Gs[(0 * 8 + u) * GPAD + b] + g_xg[(size_t)(0 * HDIM + j) * MTOT + m];
            const float gf = Gs[(1 * 8 + u) * GPAD + b] + g_xg[(size_t)(1 * HDIM + j) * MTOT + m];
            const float gg = Gs[(2 * 8 + u) * GPAD + b] + g_xg[(size_t)(2 * HDIM + j) * MTOT + m];
            const float go = Gs[(3 * 8 + u) * GPAD + b] + g_xg[(size_t)(3 * HDIM + j) * MTOT + m];

            const float c = Cs[u * 64 + b];
            const float cy = sigf(gf) * c + sigf(gi) * tanhf(gg);
            float hy = sigf(go) * tanhf(cy);
            const float hpv = hp[(size_t)b * HDIM + j];
            const float rv = Rs[u];
            hy = rv * hpv + (1.f - rv) * hy;

            Cs[u * 64 + b] = cy;
            o_t[(size_t)b * HDIM + j] = hy;
            hw[(size_t)b * 1024 + j] = __float2half_rn(hy);
            if (t == T_STEPS - 1) {
                hT_out[(size_t)b * HDIM + j] = hy;
                cT_out[(size_t)b * HDIM + j] = cy;
            }
        }

        __threadfence();
        __syncthreads();
        if (tid == 0) {
            atomicAdd(&g_ctr, 1u);
            const unsigned target = (unsigned)(t + 1) * GC;
            while (*(volatile unsigned*)&g_ctr < target) { }
        }
        __syncthreads();
    }
}

// =====================================================================
extern "C" void kernel_launch(void* const* d_in, const int* in_sizes, int n_in,
                              void* d_out, int out_size)
{
    const float* input_ = (const float*)d_in[0];
    const float* h0     = (const float*)d_in[1];
    const float* c0     = (const float*)d_in[2];
    const float* wih    = (const float*)d_in[3];
    const float* whh    = (const float*)d_in[4];
    const float* bih    = (const float*)d_in[5];
    const float* bhh    = (const float*)d_in[6];
    const float* retr   = (const float*)d_in[7];
    float* out = (float*)d_out;
    (void)in_sizes; (void)n_in; (void)out_size;

    cudaFuncSetAttribute(xgates_mma_kernel,
                         cudaFuncAttributeMaxDynamicSharedMemorySize, XSMEM);
    cudaFuncSetAttribute(recurrent_kernel,
                         cudaFuncAttributeMaxDynamicSharedMemorySize, RSMEM);

    conv_kernel<<<23040, 256>>>(wih, input_);
    xgates_mma_kernel<<<dim3(256, 32), 128, XSMEM>>>(bih, bhh);
    init_kernel<<<256, 256>>>(h0);
    recurrent_kernel<<<GC, 256, RSMEM>>>(h0, c0, whh, retr, out);
}

// round 13
// speedup vs baseline: 7.7876x; 1.0891x over previous
#include <cuda_runtime.h>
#include <cuda_bf16.h>
#include <cuda_fp16.h>
#include <math.h>

#define T_STEPS 512
#define BATCH   64
#define IDIM    1024
#define HDIM    1024
#define G4      4096
#define MTOT    (T_STEPS * BATCH)

__device__ float g_xg[(size_t)G4 * MTOT];
__device__ unsigned g_ctr;
__device__ char g_wp[(size_t)32 * 32 * 20480];    // W_ih: hi+lo fp16 tiles
__device__ char g_xp[(size_t)256 * 32 * 10240];   // X: hi fp16 tiles
__device__ __half g_hf[2 * 64 * 1024];            // h fp16, double buffer

__device__ __forceinline__ unsigned smem_u32(const void* p) {
    return (unsigned)__cvta_generic_to_shared(p);
}

#define LDM4(R0, R1, R2, R3, ADDR)                                           \
    asm volatile("ldmatrix.sync.aligned.m8n8.x4.shared.b16 {%0,%1,%2,%3},[%4];" \
                 : "=r"(R0), "=r"(R1), "=r"(R2), "=r"(R3) : "r"(ADDR))
#define MMA_F16(D, A0, A1, A2, A3, B0, B1)                                   \
    asm volatile("mma.sync.aligned.m16n8k16.row.col.f32.f16.f16.f32 "        \
                 "{%0,%1,%2,%3},{%4,%5,%6,%7},{%8,%9},{%0,%1,%2,%3};"        \
                 : "+f"(D[0]), "+f"(D[1]), "+f"(D[2]), "+f"(D[3])            \
                 : "r"(A0), "r"(A1), "r"(A2), "r"(A3), "r"(B0), "r"(B1))

__device__ __forceinline__ void cp16(unsigned dst, const void* src) {
    asm volatile("cp.async.ca.shared.global [%0], [%1], 16;" :: "r"(dst), "l"(src));
}
__device__ __forceinline__ float sigf(float x) { return 1.f / (1.f + expf(-x)); }

// =====================================================================
// prep: W -> fp16 hi/lo planes, X -> fp16 hi plane, tile layout
// =====================================================================
__global__ void __launch_bounds__(256) conv_kernel(
    const float* __restrict__ W, const float* __restrict__ X)
{
    const size_t gid = (size_t)blockIdx.x * 256 + threadIdx.x;
    if (gid < 655360) {
        const size_t pair = gid / 640;
        char* dst = g_wp + pair * 20480;
        const float* srcbase = W + (pair >> 5) * 128 * 1024 + (pair & 31) * 32;
        const unsigned o = (unsigned)(gid % 640) * 16;
        const unsigned row = o / 80, col = (o % 80) >> 1;
        union { __half h[8]; uint4 v; } H, L;
        if (col >= 32) { H.v = make_uint4(0,0,0,0); L.v = H.v; }
        else {
            const float* s = srcbase + (size_t)row * 1024 + col;
            float4 a = *(const float4*)s, b = *(const float4*)(s + 4);
            float f[8] = {a.x, a.y, a.z, a.w, b.x, b.y, b.z, b.w};
#pragma unroll
            for (int j = 0; j < 8; ++j) {
                __half hb = __float2half_rn(f[j]);
                H.h[j] = hb;
                L.h[j] = __float2half_rn(f[j] - __half2float(hb));
            }
        }
        *(uint4*)(dst + o) = H.v;
        *(uint4*)(dst + 10240 + o) = L.v;
    } else {
        const size_t pos = gid - 655360;
        const size_t pair = pos / 640;
        char* dst = g_xp + pair * 10240;
        const float* srcbase = X + (pair >> 5) * 128 * 1024 + (pair & 31) * 32;
        const unsigned o = (unsigned)(pos % 640) * 16;
        const unsigned row = o / 80, col = (o % 80) >> 1;
        union { __half h[8]; uint4 v; } H;
        if (col >= 32) H.v = make_uint4(0,0,0,0);
        else {
            const float* s = srcbase + (size_t)row * 1024 + col;
            float4 a = *(const float4*)s, b = *(const float4*)(s + 4);
            float f[8] = {a.x, a.y, a.z, a.w, b.x, b.y, b.z, b.w};
#pragma unroll
            for (int j = 0; j < 8; ++j) H.h[j] = __float2half_rn(f[j]);
        }
        *(uint4*)(dst + o) = H.v;
    }
}

// =====================================================================
// Kernel 1: x_gates GEMM, fp16 A-split, 3 stages, 1 sync/chunk, 2 CTA/SM
// =====================================================================
#define XSP   40
#define XSTG  30720
#define XSMEM (3 * XSTG)    // 92160

__global__ void __launch_bounds__(128, 2) xgates_mma_kernel(
    const float* __restrict__ bih, const float* __restrict__ bhh)
{
    extern __shared__ char xsm[];
    const unsigned sb = smem_u32(xsm);
    const int tid = threadIdx.x, lane = tid & 31, wid = tid >> 5;
    const size_t nt = blockIdx.y, mt = blockIdx.x;
    const int n0 = (int)nt * 128, m0 = (int)mt * 128;
    const int wn = (wid & 1) * 64, wm = (wid >> 1) * 64;

    float acc[4][8][4];
#pragma unroll
    for (int f = 0; f < 4; ++f)
#pragma unroll
        for (int q = 0; q < 8; ++q)
#pragma unroll
            for (int r = 0; r < 4; ++r) acc[f][q][r] = 0.f;

    unsigned offA[4], offB[4];
    {
        const int ar = wn + (lane & 15), ac = (lane >> 4) << 3;
#pragma unroll
        for (int f = 0; f < 4; ++f) offA[f] = (unsigned)(((ar + f * 16) * XSP + ac) * 2);
        const int br = wm + (lane & 7) + ((lane >> 4) << 3);
        const int bc = ((lane >> 3) & 1) << 3;
#pragma unroll
        for (int Q = 0; Q < 4; ++Q) offB[Q] = (unsigned)(((br + Q * 16) * XSP + bc) * 2);
    }

    const char* wbase = g_wp + nt * 32 * 20480;
    const char* xbase = g_xp + mt * 32 * 10240;

#define ISSUEX(C)                                                             \
    {   const char* ws = wbase + (size_t)(C) * 20480;                         \
        const char* xs = xbase + (size_t)(C) * 10240;                         \
        unsigned d = sb + ((C) % 3) * XSTG;                                   \
        _Pragma("unroll")                                                     \
        for (int i = 0; i < 10; ++i) {                                        \
            unsigned u = (unsigned)(tid + i * 128) * 16;                      \
            cp16(d + u, ws + u);                                              \
        }                                                                     \
        _Pragma("unroll")                                                     \
        for (int i = 0; i < 5; ++i) {                                         \
            unsigned u = (unsigned)(tid + i * 128) * 16;                      \
            cp16(d + 20480 + u, xs + u);                                      \
        }                                                                     \
        asm volatile("cp.async.commit_group;" ::: "memory");                  \
    }

#define COMPUTEX(BUF)                                                         \
    {   unsigned base = sb + (BUF) * XSTG;                                    \
        _Pragma("unroll")                                                     \
        for (int kk = 0; kk < 32; kk += 16) {                                 \
            unsigned kb = kk * 2;                                             \
            unsigned bh[8][2];                                                \
            _Pragma("unroll")                                                 \
            for (int Q = 0; Q < 4; ++Q) {                                     \
                unsigned r0, r1, r2, r3;                                      \
                LDM4(r0, r1, r2, r3, base + 20480 + offB[Q] + kb);            \
                bh[Q*2][0] = r0; bh[Q*2][1] = r1;                             \
                bh[Q*2+1][0] = r2; bh[Q*2+1][1] = r3;                         \
            }                                                                 \
            _Pragma("unroll")                                                 \
            for (int f = 0; f < 4; ++f) {                                     \
                unsigned a0, a1, a2, a3, c0, c1, c2, c3;                      \
                LDM4(a0, a1, a2, a3, base + offA[f] + kb);                    \
                LDM4(c0, c1, c2, c3, base + 10240 + offA[f] + kb);            \
                _Pragma("unroll")                                             \
                for (int q = 0; q < 8; ++q) {                                 \
                    MMA_F16(acc[f][q], a0, a1, a2, a3, bh[q][0], bh[q][1]);   \
                    MMA_F16(acc[f][q], c0, c1, c2, c3, bh[q][0], bh[q][1]);   \
                } } } }

    // 3 stages, depth-2 prefetch, single sync per chunk
    ISSUEX(0); ISSUEX(1);
    for (int c = 0; c < 32; ++c) {
        if (c < 31)
            asm volatile("cp.async.wait_group 1;" ::: "memory");
        else
            asm volatile("cp.async.wait_group 0;" ::: "memory");
        __syncthreads();
        if (c + 2 < 32) ISSUEX(c + 2);
        COMPUTEX(c % 3);
    }
#undef ISSUEX
#undef COMPUTEX

    __syncthreads();
    const int erow = lane >> 2, ecol = (lane & 3) * 2;
#pragma unroll
    for (int f = 0; f < 4; ++f) {
        const int n = n0 + wn + f * 16 + erow;
        const float b0 = bih[n] + bhh[n];
        const float b8 = bih[n + 8] + bhh[n + 8];
#pragma unroll
        for (int q = 0; q < 8; ++q) {
            const int m = m0 + wm + q * 8 + ecol;
            *(float2*)(g_xg + (size_t)n * MTOT + m) =
                make_float2(acc[f][q][0] + b0, acc[f][q][1] + b0);
            *(float2*)(g_xg + (size_t)(n + 8) * MTOT + m) =
                make_float2(acc[f][q][2] + b8, acc[f][q][3] + b8);
        }
    }
}

// =====================================================================
// init: reset barrier + convert h0 -> g_hf buf 0 (fp16)
// =====================================================================
__global__ void init_kernel(const float* __restrict__ h0) {
    if (blockIdx.x == 0 && threadIdx.x == 0) g_ctr = 0u;
    const int idx = blockIdx.x * 256 + threadIdx.x;
    const int b = idx >> 10, j = idx & 1023;
    g_hf[(size_t)b * 1024 + j] = __float2half_rn(h0[(size_t)b * HDIM + j]);
}

// =====================================================================
// Kernel 2: recurrent. W_hh fp16 hi/lo, h fp16. KC=128 (8 chunks),
// 3 stages, 1 sync/chunk, epilogue loads hoisted to step start.
// smem: Whi 66048 | Wlo 66048 | Ht 3x17408 | Gs 8448 | Cs 2048 | Rs 32
// =====================================================================
#define GC 128
#define WST    1032
#define WHI_O  0
#define WLO_O  66048
#define HT_O   132096
#define HSTG   17408                 // 64 rows x 272 B
#define GS_O   (HT_O + 3 * HSTG)     // 184320
#define CS_O   (GS_O + 8448)         // 192768
#define RS_O   (CS_O + 2048)         // 194816
#define RSMEM  (RS_O + 32)           // 194848
#define GPAD   66

__global__ void __launch_bounds__(256, 1) recurrent_kernel(
    const float* __restrict__ h0raw, const float* __restrict__ c0,
    const float* __restrict__ whh, const float* __restrict__ retr,
    float* __restrict__ out)
{
    extern __shared__ char s[];
    const unsigned sb = smem_u32(s);
    float* Gs = (float*)(s + GS_O);
    float* Cs = (float*)(s + CS_O);
    float* Rs = (float*)(s + RS_O);

    const int tid = threadIdx.x, lane = tid & 31, wid = tid >> 5;
    const int j0 = blockIdx.x * 8;

    for (int idx = tid; idx < 32 * 256; idx += 256) {
        const int r = idx >> 8, kq = (idx & 255) << 2;
        const int g = r >> 3, u = r & 7;
        const float4 v = *(const float4*)(whh + (size_t)(g * HDIM + j0 + u) * HDIM + kq);
        const float f[4] = {v.x, v.y, v.z, v.w};
        __half hi[4], lo[4];
#pragma unroll
        for (int j = 0; j < 4; ++j) {
            hi[j] = __float2half_rn(f[j]);
            lo[j] = __float2half_rn(f[j] - __half2float(hi[j]));
        }
        *(uint2*)(s + WHI_O + (r * WST + kq) * 2) = *(uint2*)hi;
        *(uint2*)(s + WLO_O + (r * WST + kq) * 2) = *(uint2*)lo;
    }
    if (tid < 8) Rs[tid] = retr[j0 + tid];
    for (int idx = tid; idx < 512; idx += 256) {
        const int u = idx & 7, b = idx >> 3;
        Cs[u * 64 + b] = c0[(size_t)b * HDIM + j0 + u];
    }
    __syncthreads();

    const int mtile = wid & 1;
    const int npair = wid >> 1;
    const unsigned offA =
        (unsigned)(((mtile * 16 + (lane & 15)) * WST + ((lane >> 4) << 3)) * 2);
    const unsigned offB =
        (unsigned)((npair * 16 + (lane & 7) + ((lane >> 4) << 3)) * 272 +
                   ((((lane >> 3) & 1) << 3) * 2));

    // epilogue cell mapping (fixed per thread)
    const int u0 = tid & 7,          b0 = tid >> 3;          // cell 0
    const int u1 = (tid + 256) & 7,  b1 = (tid + 256) >> 3;  // cell 1

    float* hT_out = out + (size_t)T_STEPS * BATCH * HDIM;
    float* cT_out = hT_out + (size_t)BATCH * HDIM;

    for (int t = 0; t < T_STEPS; ++t) {
        const float* hp = (t == 0) ? h0raw : (out + (size_t)(t - 1) * BATCH * HDIM);
        const char* hsrc = (const char*)g_hf + (size_t)(t & 1) * 131072;

        // hoist epilogue global loads: xg (8) + h_prev (2)
        const size_t m0_ = (size_t)t * BATCH + b0;
        const size_t m1_ = (size_t)t * BATCH + b1;
        float xgr[8], hpr[2];
#pragma unroll
        for (int g = 0; g < 4; ++g) {
            xgr[g]     = __ldg(g_xg + (size_t)(g * HDIM + j0 + u0) * MTOT + m0_);
            xgr[4 + g] = __ldg(g_xg + (size_t)(g * HDIM + j0 + u1) * MTOT + m1_);
        }
        hpr[0] = __ldg(hp + (size_t)b0 * HDIM + j0 + u0);
        hpr[1] = __ldg(hp + (size_t)b1 * HDIM + j0 + u1);

        // h chunk: 64 rows x 128 k fp16 = 16KB -> 1024 x 16B, 4/thread
#define ISSUER(C)                                                            \
        {   const unsigned dstb = sb + HT_O + ((C) % 3) * HSTG;              \
            _Pragma("unroll")                                                \
            for (int i = 0; i < 4; ++i) {                                    \
                const int u = tid + i * 256;                                 \
                const int row = u >> 4, cg = u & 15;                         \
                cp16(dstb + row * 272 + cg * 16,                             \
                     hsrc + (size_t)row * 2048 + (C) * 256 + cg * 16);       \
            }                                                                \
            asm volatile("cp.async.commit_group;" ::: "memory");             \
        }

        ISSUER(0); ISSUER(1);

        float acc0[4] = {0.f, 0.f, 0.f, 0.f};
        float acc1[4] = {0.f, 0.f, 0.f, 0.f};

        for (int c = 0; c < 8; ++c) {
            if (c < 7)
                asm volatile("cp.async.wait_group 1;" ::: "memory");
            else
                asm volatile("cp.async.wait_group 0;" ::: "memory");
            __syncthreads();
            if (c + 2 < 8) ISSUER(c + 2);

            const unsigned stb = sb + HT_O + (c % 3) * HSTG;
#pragma unroll
            for (int ks = 0; ks < 8; ++ks) {
                const unsigned ka = (unsigned)((c * 128 + ks * 16) * 2);
                unsigned ah0, ah1, ah2, ah3, al0, al1, al2, al3;
                unsigned bh0, bh1, bh2, bh3;
                LDM4(ah0, ah1, ah2, ah3, sb + WHI_O + offA + ka);
                LDM4(al0, al1, al2, al3, sb + WLO_O + offA + ka);
                LDM4(bh0, bh1, bh2, bh3, stb + offB + ks * 32);
                MMA_F16(acc0, ah0, ah1, ah2, ah3, bh0, bh1);
                MMA_F16(acc1, ah0, ah1, ah2, ah3, bh2, bh3);
                MMA_F16(acc0, al0, al1, al2, al3, bh0, bh1);
                MMA_F16(acc1, al0, al1, al2, al3, bh2, bh3);
            }
        }
#undef ISSUER

        {
            const int row = mtile * 16 + (lane >> 2);
            const int col = npair * 16 + (lane & 3) * 2;
            Gs[row * GPAD + col]           = acc0[0];
            Gs[row * GPAD + col + 1]       = acc0[1];
            Gs[(row + 8) * GPAD + col]     = acc0[2];
            Gs[(row + 8) * GPAD + col + 1] = acc0[3];
            Gs[row * GPAD + col + 8]       = acc1[0];
            Gs[row * GPAD + col + 9]       = acc1[1];
            Gs[(row + 8) * GPAD + col + 8] = acc1[2];
            Gs[(row + 8) * GPAD + col + 9] = acc1[3];
        }
        __syncthreads();

        float* o_t = out + (size_t)t * BATCH * HDIM;
        __half* hw = g_hf + (size_t)((t + 1) & 1) * 65536;
#pragma unroll
        for (int c2 = 0; c2 < 2; ++c2) {
            const int u = c2 ? u1 : u0, b = c2 ? b1 : b0;
            const int j = j0 + u;

            const float gi = Gs[(0 * 8 + u) * GPAD + b] + xgr[c2 * 4 + 0];
            const float gf = Gs[(1 * 8 + u) * GPAD + b] + xgr[c2 * 4 + 1];
            const float gg = Gs[(2 * 8 + u) * GPAD + b] + xgr[c2 * 4 + 2];
            const float go = Gs[(3 * 8 + u) * GPAD + b] + xgr[c2 * 4 + 3];

            const float c = Cs[u * 64 + b];
            const float cy = sigf(gf) * c + sigf(gi) * tanhf(gg);
            float hy = sigf(go) * tanhf(cy);
            const float rv = Rs[u];
            hy = rv * hpr[c2] + (1.f - rv) * hy;

            Cs[u * 64 + b] = cy;
            o_t[(size_t)b * HDIM + j] = hy;
            hw[(size_t)b * 1024 + j] = __float2half_rn(hy);
            if (t == T_STEPS - 1) {
                hT_out[(size_t)b * HDIM + j] = hy;
                cT_out[(size_t)b * HDIM + j] = cy;
            }
        }

        __threadfence();
        __syncthreads();
        if (tid == 0) {
            atomicAdd(&g_ctr, 1u);
            const unsigned target = (unsigned)(t + 1) * GC;
            while (*(volatile unsigned*)&g_ctr < target) { }
        }
        __syncthreads();
    }
}

// =====================================================================
extern "C" void kernel_launch(void* const* d_in, const int* in_sizes, int n_in,
                              void* d_out, int out_size)
{
    const float* input_ = (const float*)d_in[0];
    const float* h0     = (const float*)d_in[1];
    const float* c0     = (const float*)d_in[2];
    const float* wih    = (const float*)d_in[3];
    const float* whh    = (const float*)d_in[4];
    const float* bih    = (const float*)d_in[5];
    const float* bhh    = (const float*)d_in[6];
    const float* retr   = (const float*)d_in[7];
    float* out = (float*)d_out;
    (void)in_sizes; (void)n_in; (void)out_size;

    cudaFuncSetAttribute(xgates_mma_kernel,
                         cudaFuncAttributeMaxDynamicSharedMemorySize, XSMEM);
    cudaFuncSetAttribute(recurrent_kernel,
                         cudaFuncAttributeMaxDynamicSharedMemorySize, RSMEM);

    conv_kernel<<<23040, 256>>>(wih, input_);
    xgates_mma_kernel<<<dim3(256, 32), 128, XSMEM>>>(bih, bhh);
    init_kernel<<<256, 256>>>(h0);
    recurrent_kernel<<<GC, 256, RSMEM>>>(h0, c0, whh, retr, out);
}

// round 14
// speedup vs baseline: 8.8727x; 1.1393x over previous
#include <cuda_runtime.h>
#include <cuda_bf16.h>
#include <cuda_fp16.h>
#include <math.h>

#define T_STEPS 512
#define BATCH   64
#define IDIM    1024
#define HDIM    1024
#define G4      4096
#define MTOT    (T_STEPS * BATCH)

__device__ float g_xg[(size_t)G4 * MTOT];
__device__ unsigned g_ctr;
__device__ char g_wp[(size_t)32 * 32 * 10240];    // W_ih: hi fp16 tiles only
__device__ char g_xp[(size_t)256 * 32 * 10240];   // X: hi fp16 tiles
__device__ __half g_hf[2 * 64 * 1024];            // h fp16, double buffer

__device__ __forceinline__ unsigned smem_u32(const void* p) {
    return (unsigned)__cvta_generic_to_shared(p);
}

#define LDM4(R0, R1, R2, R3, ADDR)                                           \
    asm volatile("ldmatrix.sync.aligned.m8n8.x4.shared.b16 {%0,%1,%2,%3},[%4];" \
                 : "=r"(R0), "=r"(R1), "=r"(R2), "=r"(R3) : "r"(ADDR))
#define MMA_F16(D, A0, A1, A2, A3, B0, B1)                                   \
    asm volatile("mma.sync.aligned.m16n8k16.row.col.f32.f16.f16.f32 "        \
                 "{%0,%1,%2,%3},{%4,%5,%6,%7},{%8,%9},{%0,%1,%2,%3};"        \
                 : "+f"(D[0]), "+f"(D[1]), "+f"(D[2]), "+f"(D[3])            \
                 : "r"(A0), "r"(A1), "r"(A2), "r"(A3), "r"(B0), "r"(B1))

__device__ __forceinline__ void cp16(unsigned dst, const void* src) {
    asm volatile("cp.async.ca.shared.global [%0], [%1], 16;" :: "r"(dst), "l"(src));
}
__device__ __forceinline__ float sigf(float x) { return 1.f / (1.f + expf(-x)); }

// =====================================================================
// prep: W -> fp16 hi plane, X -> fp16 hi plane, tile layout
// =====================================================================
__global__ void __launch_bounds__(256) conv_kernel(
    const float* __restrict__ W, const float* __restrict__ X)
{
    const size_t gid = (size_t)blockIdx.x * 256 + threadIdx.x;
    const float* srcbase;
    char* dst;
    unsigned o;
    if (gid < 655360) {
        const size_t pair = gid / 640;
        dst = g_wp + pair * 10240;
        srcbase = W + (pair >> 5) * 128 * 1024 + (pair & 31) * 32;
        o = (unsigned)(gid % 640) * 16;
    } else {
        const size_t pos = gid - 655360;
        const size_t pair = pos / 640;
        dst = g_xp + pair * 10240;
        srcbase = X + (pair >> 5) * 128 * 1024 + (pair & 31) * 32;
        o = (unsigned)(pos % 640) * 16;
    }
    const unsigned row = o / 80, col = (o % 80) >> 1;
    union { __half h[8]; uint4 v; } H;
    if (col >= 32) H.v = make_uint4(0, 0, 0, 0);
    else {
        const float* s = srcbase + (size_t)row * 1024 + col;
        float4 a = *(const float4*)s, b = *(const float4*)(s + 4);
        float f[8] = {a.x, a.y, a.z, a.w, b.x, b.y, b.z, b.w};
#pragma unroll
        for (int j = 0; j < 8; ++j) H.h[j] = __float2half_rn(f[j]);
    }
    *(uint4*)(dst + o) = H.v;
}

// =====================================================================
// Kernel 1: x_gates GEMM, single-product fp16, 3 stages, 1 sync/chunk,
// 2 CTAs/SM. Stage: W 10240 | X 10240
// =====================================================================
#define XSP   40
#define XSTG  20480
#define XSMEM (3 * XSTG)    // 61440

__global__ void __launch_bounds__(128, 2) xgates_mma_kernel(
    const float* __restrict__ bih, const float* __restrict__ bhh)
{
    extern __shared__ char xsm[];
    const unsigned sb = smem_u32(xsm);
    const int tid = threadIdx.x, lane = tid & 31, wid = tid >> 5;
    const size_t nt = blockIdx.y, mt = blockIdx.x;
    const int n0 = (int)nt * 128, m0 = (int)mt * 128;
    const int wn = (wid & 1) * 64, wm = (wid >> 1) * 64;

    float acc[4][8][4];
#pragma unroll
    for (int f = 0; f < 4; ++f)
#pragma unroll
        for (int q = 0; q < 8; ++q)
#pragma unroll
            for (int r = 0; r < 4; ++r) acc[f][q][r] = 0.f;

    unsigned offA[4], offB[4];
    {
        const int ar = wn + (lane & 15), ac = (lane >> 4) << 3;
#pragma unroll
        for (int f = 0; f < 4; ++f) offA[f] = (unsigned)(((ar + f * 16) * XSP + ac) * 2);
        const int br = wm + (lane & 7) + ((lane >> 4) << 3);
        const int bc = ((lane >> 3) & 1) << 3;
#pragma unroll
        for (int Q = 0; Q < 4; ++Q) offB[Q] = (unsigned)(((br + Q * 16) * XSP + bc) * 2);
    }

    const char* wbase = g_wp + nt * 32 * 10240;
    const char* xbase = g_xp + mt * 32 * 10240;

#define ISSUEX(C)                                                             \
    {   const char* ws = wbase + (size_t)(C) * 10240;                         \
        const char* xs = xbase + (size_t)(C) * 10240;                         \
        unsigned d = sb + ((C) % 3) * XSTG;                                   \
        _Pragma("unroll")                                                     \
        for (int i = 0; i < 5; ++i) {                                         \
            unsigned u = (unsigned)(tid + i * 128) * 16;                      \
            cp16(d + u, ws + u);                                              \
            cp16(d + 10240 + u, xs + u);                                      \
        }                                                                     \
        asm volatile("cp.async.commit_group;" ::: "memory");                  \
    }

#define COMPUTEX(BUF)                                                         \
    {   unsigned base = sb + (BUF) * XSTG;                                    \
        _Pragma("unroll")                                                     \
        for (int kk = 0; kk < 32; kk += 16) {                                 \
            unsigned kb = kk * 2;                                             \
            unsigned bh[8][2];                                                \
            _Pragma("unroll")                                                 \
            for (int Q = 0; Q < 4; ++Q) {                                     \
                unsigned r0, r1, r2, r3;                                      \
                LDM4(r0, r1, r2, r3, base + 10240 + offB[Q] + kb);            \
                bh[Q*2][0] = r0; bh[Q*2][1] = r1;                             \
                bh[Q*2+1][0] = r2; bh[Q*2+1][1] = r3;                         \
            }                                                                 \
            _Pragma("unroll")                                                 \
            for (int f = 0; f < 4; ++f) {                                     \
                unsigned a0, a1, a2, a3;                                      \
                LDM4(a0, a1, a2, a3, base + offA[f] + kb);                    \
                _Pragma("unroll")                                             \
                for (int q = 0; q < 8; ++q)                                   \
                    MMA_F16(acc[f][q], a0, a1, a2, a3, bh[q][0], bh[q][1]);   \
            } } }

    ISSUEX(0); ISSUEX(1);
    for (int c = 0; c < 32; ++c) {
        if (c < 31)
            asm volatile("cp.async.wait_group 1;" ::: "memory");
        else
            asm volatile("cp.async.wait_group 0;" ::: "memory");
        __syncthreads();
        if (c + 2 < 32) ISSUEX(c + 2);
        COMPUTEX(c % 3);
    }
#undef ISSUEX
#undef COMPUTEX

    __syncthreads();
    const int erow = lane >> 2, ecol = (lane & 3) * 2;
#pragma unroll
    for (int f = 0; f < 4; ++f) {
        const int n = n0 + wn + f * 16 + erow;
        const float b0 = bih[n] + bhh[n];
        const float b8 = bih[n + 8] + bhh[n + 8];
#pragma unroll
        for (int q = 0; q < 8; ++q) {
            const int m = m0 + wm + q * 8 + ecol;
            *(float2*)(g_xg + (size_t)n * MTOT + m) =
                make_float2(acc[f][q][0] + b0, acc[f][q][1] + b0);
            *(float2*)(g_xg + (size_t)(n + 8) * MTOT + m) =
                make_float2(acc[f][q][2] + b8, acc[f][q][3] + b8);
        }
    }
}

// =====================================================================
// init: reset barrier + convert h0 -> g_hf buf 0 (fp16)
// =====================================================================
__global__ void init_kernel(const float* __restrict__ h0) {
    if (blockIdx.x == 0 && threadIdx.x == 0) g_ctr = 0u;
    const int idx = blockIdx.x * 256 + threadIdx.x;
    const int b = idx >> 10, j = idx & 1023;
    g_hf[(size_t)b * 1024 + j] = __float2half_rn(h0[(size_t)b * HDIM + j]);
}

// =====================================================================
// Kernel 2: recurrent (R13, known-good, unchanged): W fp16 hi/lo,
// h fp16, KC=128, 3 stages, hoisted epilogue loads
// =====================================================================
#define GC 128
#define WST    1032
#define WHI_O  0
#define WLO_O  66048
#define HT_O   132096
#define HSTG   17408
#define GS_O   (HT_O + 3 * HSTG)
#define CS_O   (GS_O + 8448)
#define RS_O   (CS_O + 2048)
#define RSMEM  (RS_O + 32)
#define GPAD   66

__global__ void __launch_bounds__(256, 1) recurrent_kernel(
    const float* __restrict__ h0raw, const float* __restrict__ c0,
    const float* __restrict__ whh, const float* __restrict__ retr,
    float* __restrict__ out)
{
    extern __shared__ char s[];
    const unsigned sb = smem_u32(s);
    float* Gs = (float*)(s + GS_O);
    float* Cs = (float*)(s + CS_O);
    float* Rs = (float*)(s + RS_O);

    const int tid = threadIdx.x, lane = tid & 31, wid = tid >> 5;
    const int j0 = blockIdx.x * 8;

    for (int idx = tid; idx < 32 * 256; idx += 256) {
        const int r = idx >> 8, kq = (idx & 255) << 2;
        const int g = r >> 3, u = r & 7;
        const float4 v = *(const float4*)(whh + (size_t)(g * HDIM + j0 + u) * HDIM + kq);
        const float f[4] = {v.x, v.y, v.z, v.w};
        __half hi[4], lo[4];
#pragma unroll
        for (int j = 0; j < 4; ++j) {
            hi[j] = __float2half_rn(f[j]);
            lo[j] = __float2half_rn(f[j] - __half2float(hi[j]));
        }
        *(uint2*)(s + WHI_O + (r * WST + kq) * 2) = *(uint2*)hi;
        *(uint2*)(s + WLO_O + (r * WST + kq) * 2) = *(uint2*)lo;
    }
    if (tid < 8) Rs[tid] = retr[j0 + tid];
    for (int idx = tid; idx < 512; idx += 256) {
        const int u = idx & 7, b = idx >> 3;
        Cs[u * 64 + b] = c0[(size_t)b * HDIM + j0 + u];
    }
    __syncthreads();

    const int mtile = wid & 1;
    const int npair = wid >> 1;
    const unsigned offA =
        (unsigned)(((mtile * 16 + (lane & 15)) * WST + ((lane >> 4) << 3)) * 2);
    const unsigned offB =
        (unsigned)((npair * 16 + (lane & 7) + ((lane >> 4) << 3)) * 272 +
                   ((((lane >> 3) & 1) << 3) * 2));

    const int u0 = tid & 7,          b0 = tid >> 3;
    const int u1 = (tid + 256) & 7,  b1 = (tid + 256) >> 3;

    float* hT_out = out + (size_t)T_STEPS * BATCH * HDIM;
    float* cT_out = hT_out + (size_t)BATCH * HDIM;

    for (int t = 0; t < T_STEPS; ++t) {
        const float* hp = (t == 0) ? h0raw : (out + (size_t)(t - 1) * BATCH * HDIM);
        const char* hsrc = (const char*)g_hf + (size_t)(t & 1) * 131072;

        const size_t m0_ = (size_t)t * BATCH + b0;
        const size_t m1_ = (size_t)t * BATCH + b1;
        float xgr[8], hpr[2];
#pragma unroll
        for (int g = 0; g < 4; ++g) {
            xgr[g]     = __ldg(g_xg + (size_t)(g * HDIM + j0 + u0) * MTOT + m0_);
            xgr[4 + g] = __ldg(g_xg + (size_t)(g * HDIM + j0 + u1) * MTOT + m1_);
        }
        hpr[0] = __ldg(hp + (size_t)b0 * HDIM + j0 + u0);
        hpr[1] = __ldg(hp + (size_t)b1 * HDIM + j0 + u1);

#define ISSUER(C)                                                            \
        {   const unsigned dstb = sb + HT_O + ((C) % 3) * HSTG;              \
            _Pragma("unroll")                                                \
            for (int i = 0; i < 4; ++i) {                                    \
                const int u = tid + i * 256;                                 \
                const int row = u >> 4, cg = u & 15;                         \
                cp16(dstb + row * 272 + cg * 16,                             \
                     hsrc + (size_t)row * 2048 + (C) * 256 + cg * 16);       \
            }                                                                \
            asm volatile("cp.async.commit_group;" ::: "memory");             \
        }

        ISSUER(0); ISSUER(1);

        float acc0[4] = {0.f, 0.f, 0.f, 0.f};
        float acc1[4] = {0.f, 0.f, 0.f, 0.f};

        for (int c = 0; c < 8; ++c) {
            if (c < 7)
                asm volatile("cp.async.wait_group 1;" ::: "memory");
            else
                asm volatile("cp.async.wait_group 0;" ::: "memory");
            __syncthreads();
            if (c + 2 < 8) ISSUER(c + 2);

            const unsigned stb = sb + HT_O + (c % 3) * HSTG;
#pragma unroll
            for (int ks = 0; ks < 8; ++ks) {
                const unsigned ka = (unsigned)((c * 128 + ks * 16) * 2);
                unsigned ah0, ah1, ah2, ah3, al0, al1, al2, al3;
                unsigned bh0, bh1, bh2, bh3;
                LDM4(ah0, ah1, ah2, ah3, sb + WHI_O + offA + ka);
                LDM4(al0, al1, al2, al3, sb + WLO_O + offA + ka);
                LDM4(bh0, bh1, bh2, bh3, stb + offB + ks * 32);
                MMA_F16(acc0, ah0, ah1, ah2, ah3, bh0, bh1);
                MMA_F16(acc1, ah0, ah1, ah2, ah3, bh2, bh3);
                MMA_F16(acc0, al0, al1, al2, al3, bh0, bh1);
                MMA_F16(acc1, al0, al1, al2, al3, bh2, bh3);
            }
        }
#undef ISSUER

        {
            const int row = mtile * 16 + (lane >> 2);
            const int col = npair * 16 + (lane & 3) * 2;
            Gs[row * GPAD + col]           = acc0[0];
            Gs[row * GPAD + col + 1]       = acc0[1];
            Gs[(row + 8) * GPAD + col]     = acc0[2];
            Gs[(row + 8) * GPAD + col + 1] = acc0[3];
            Gs[row * GPAD + col + 8]       = acc1[0];
            Gs[row * GPAD + col + 9]       = acc1[1];
            Gs[(row + 8) * GPAD + col + 8] = acc1[2];
            Gs[(row + 8) * GPAD + col + 9] = acc1[3];
        }
        __syncthreads();

        float* o_t = out + (size_t)t * BATCH * HDIM;
        __half* hw = g_hf + (size_t)((t + 1) & 1) * 65536;
#pragma unroll
        for (int c2 = 0; c2 < 2; ++c2) {
            const int u = c2 ? u1 : u0, b = c2 ? b1 : b0;
            const int j = j0 + u;

            const float gi = Gs[(0 * 8 + u) * GPAD + b] + xgr[c2 * 4 + 0];
            const float gf = Gs[(1 * 8 + u) * GPAD + b] + xgr[c2 * 4 + 1];
            const float gg = Gs[(2 * 8 + u) * GPAD + b] + xgr[c2 * 4 + 2];
            const float go = Gs[(3 * 8 + u) * GPAD + b] + xgr[c2 * 4 + 3];

            const float c = Cs[u * 64 + b];
            const float cy = sigf(gf) * c + sigf(gi) * tanhf(gg);
            float hy = sigf(go) * tanhf(cy);
            const float rv = Rs[u];
            hy = rv * hpr[c2] + (1.f - rv) * hy;

            Cs[u * 64 + b] = cy;
            o_t[(size_t)b * HDIM + j] = hy;
            hw[(size_t)b * 1024 + j] = __float2half_rn(hy);
            if (t == T_STEPS - 1) {
                hT_out[(size_t)b * HDIM + j] = hy;
                cT_out[(size_t)b * HDIM + j] = cy;
            }
        }

        __threadfence();
        __syncthreads();
        if (tid == 0) {
            atomicAdd(&g_ctr, 1u);
            const unsigned target = (unsigned)(t + 1) * GC;
            while (*(volatile unsigned*)&g_ctr < target) { }
        }
        __syncthreads();
    }
}

// =====================================================================
extern "C" void kernel_launch(void* const* d_in, const int* in_sizes, int n_in,
                              void* d_out, int out_size)
{
    const float* input_ = (const float*)d_in[0];
    const float* h0     = (const float*)d_in[1];
    const float* c0     = (const float*)d_in[2];
    const float* wih    = (const float*)d_in[3];
    const float* whh    = (const float*)d_in[4];
    const float* bih    = (const float*)d_in[5];
    const float* bhh    = (const float*)d_in[6];
    const float* retr   = (const float*)d_in[7];
    float* out = (float*)d_out;
    (void)in_sizes; (void)n_in; (void)out_size;

    cudaFuncSetAttribute(xgates_mma_kernel,
                         cudaFuncAttributeMaxDynamicSharedMemorySize, XSMEM);
    cudaFuncSetAttribute(recurrent_kernel,
                         cudaFuncAttributeMaxDynamicSharedMemorySize, RSMEM);

    conv_kernel<<<23040, 256>>>(wih, input_);
    xgates_mma_kernel<<<dim3(256, 32), 128, XSMEM>>>(bih, bhh);
    init_kernel<<<256, 256>>>(h0);
    recurrent_kernel<<<GC, 256, RSMEM>>>(h0, c0, whh, retr, out);
}

// round 15
// speedup vs baseline: 11.1728x; 1.2592x over previous
#include <cuda_runtime.h>
#include <cuda_bf16.h>
#include <cuda_fp16.h>
#include <math.h>

#define T_STEPS 512
#define BATCH   64
#define IDIM    1024
#define HDIM    1024
#define G4      4096
#define MTOT    (T_STEPS * BATCH)

__device__ float g_xg[(size_t)G4 * MTOT];
__device__ unsigned g_ctr;
__device__ char g_wp[(size_t)32 * 32 * 10240];    // W_ih: hi fp16 tiles
__device__ char g_xp[(size_t)256 * 32 * 10240];   // X: hi fp16 tiles
__device__ __half g_hf[2 * 64 * 1024];            // h fp16, double buffer

__device__ __forceinline__ unsigned smem_u32(const void* p) {
    return (unsigned)__cvta_generic_to_shared(p);
}

#define LDM4(R0, R1, R2, R3, ADDR)                                           \
    asm volatile("ldmatrix.sync.aligned.m8n8.x4.shared.b16 {%0,%1,%2,%3},[%4];" \
                 : "=r"(R0), "=r"(R1), "=r"(R2), "=r"(R3) : "r"(ADDR))
#define MMA_F16(D, A0, A1, A2, A3, B0, B1)                                   \
    asm volatile("mma.sync.aligned.m16n8k16.row.col.f32.f16.f16.f32 "        \
                 "{%0,%1,%2,%3},{%4,%5,%6,%7},{%8,%9},{%0,%1,%2,%3};"        \
                 : "+f"(D[0]), "+f"(D[1]), "+f"(D[2]), "+f"(D[3])            \
                 : "r"(A0), "r"(A1), "r"(A2), "r"(A3), "r"(B0), "r"(B1))

__device__ __forceinline__ void cp16(unsigned dst, const void* src) {
    asm volatile("cp.async.ca.shared.global [%0], [%1], 16;" :: "r"(dst), "l"(src));
}
__device__ __forceinline__ float sigf(float x) { return 1.f / (1.f + expf(-x)); }

// =====================================================================
// prep: W -> fp16 hi plane, X -> fp16 hi plane, tile layout (unchanged)
// =====================================================================
__global__ void __launch_bounds__(256) conv_kernel(
    const float* __restrict__ W, const float* __restrict__ X)
{
    const size_t gid = (size_t)blockIdx.x * 256 + threadIdx.x;
    const float* srcbase;
    char* dst;
    unsigned o;
    if (gid < 655360) {
        const size_t pair = gid / 640;
        dst = g_wp + pair * 10240;
        srcbase = W + (pair >> 5) * 128 * 1024 + (pair & 31) * 32;
        o = (unsigned)(gid % 640) * 16;
    } else {
        const size_t pos = gid - 655360;
        const size_t pair = pos / 640;
        dst = g_xp + pair * 10240;
        srcbase = X + (pair >> 5) * 128 * 1024 + (pair & 31) * 32;
        o = (unsigned)(pos % 640) * 16;
    }
    const unsigned row = o / 80, col = (o % 80) >> 1;
    union { __half h[8]; uint4 v; } H;
    if (col >= 32) H.v = make_uint4(0, 0, 0, 0);
    else {
        const float* s = srcbase + (size_t)row * 1024 + col;
        float4 a = *(const float4*)s, b = *(const float4*)(s + 4);
        float f[8] = {a.x, a.y, a.z, a.w, b.x, b.y, b.z, b.w};
#pragma unroll
        for (int j = 0; j < 8; ++j) H.h[j] = __float2half_rn(f[j]);
    }
    *(uint4*)(dst + o) = H.v;
}

// =====================================================================
// Kernel 1: x_gates GEMM (R14, known-good, unchanged)
// =====================================================================
#define XSP   40
#define XSTG  20480
#define XSMEM (3 * XSTG)

__global__ void __launch_bounds__(128, 2) xgates_mma_kernel(
    const float* __restrict__ bih, const float* __restrict__ bhh)
{
    extern __shared__ char xsm[];
    const unsigned sb = smem_u32(xsm);
    const int tid = threadIdx.x, lane = tid & 31, wid = tid >> 5;
    const size_t nt = blockIdx.y, mt = blockIdx.x;
    const int n0 = (int)nt * 128, m0 = (int)mt * 128;
    const int wn = (wid & 1) * 64, wm = (wid >> 1) * 64;

    float acc[4][8][4];
#pragma unroll
    for (int f = 0; f < 4; ++f)
#pragma unroll
        for (int q = 0; q < 8; ++q)
#pragma unroll
            for (int r = 0; r < 4; ++r) acc[f][q][r] = 0.f;

    unsigned offA[4], offB[4];
    {
        const int ar = wn + (lane & 15), ac = (lane >> 4) << 3;
#pragma unroll
        for (int f = 0; f < 4; ++f) offA[f] = (unsigned)(((ar + f * 16) * XSP + ac) * 2);
        const int br = wm + (lane & 7) + ((lane >> 4) << 3);
        const int bc = ((lane >> 3) & 1) << 3;
#pragma unroll
        for (int Q = 0; Q < 4; ++Q) offB[Q] = (unsigned)(((br + Q * 16) * XSP + bc) * 2);
    }

    const char* wbase = g_wp + nt * 32 * 10240;
    const char* xbase = g_xp + mt * 32 * 10240;

#define ISSUEX(C)                                                             \
    {   const char* ws = wbase + (size_t)(C) * 10240;                         \
        const char* xs = xbase + (size_t)(C) * 10240;                         \
        unsigned d = sb + ((C) % 3) * XSTG;                                   \
        _Pragma("unroll")                                                     \
        for (int i = 0; i < 5; ++i) {                                         \
            unsigned u = (unsigned)(tid + i * 128) * 16;                      \
            cp16(d + u, ws + u);                                              \
            cp16(d + 10240 + u, xs + u);                                      \
        }                                                                     \
        asm volatile("cp.async.commit_group;" ::: "memory");                  \
    }

#define COMPUTEX(BUF)                                                         \
    {   unsigned base = sb + (BUF) * XSTG;                                    \
        _Pragma("unroll")                                                     \
        for (int kk = 0; kk < 32; kk += 16) {                                 \
            unsigned kb = kk * 2;                                             \
            unsigned bh[8][2];                                                \
            _Pragma("unroll")                                                 \
            for (int Q = 0; Q < 4; ++Q) {                                     \
                unsigned r0, r1, r2, r3;                                      \
                LDM4(r0, r1, r2, r3, base + 10240 + offB[Q] + kb);            \
                bh[Q*2][0] = r0; bh[Q*2][1] = r1;                             \
                bh[Q*2+1][0] = r2; bh[Q*2+1][1] = r3;                         \
            }                                                                 \
            _Pragma("unroll")                                                 \
            for (int f = 0; f < 4; ++f) {                                     \
                unsigned a0, a1, a2, a3;                                      \
                LDM4(a0, a1, a2, a3, base + offA[f] + kb);                    \
                _Pragma("unroll")                                             \
                for (int q = 0; q < 8; ++q)                                   \
                    MMA_F16(acc[f][q], a0, a1, a2, a3, bh[q][0], bh[q][1]);   \
            } } }

    ISSUEX(0); ISSUEX(1);
    for (int c = 0; c < 32; ++c) {
        if (c < 31)
            asm volatile("cp.async.wait_group 1;" ::: "memory");
        else
            asm volatile("cp.async.wait_group 0;" ::: "memory");
        __syncthreads();
        if (c + 2 < 32) ISSUEX(c + 2);
        COMPUTEX(c % 3);
    }
#undef ISSUEX
#undef COMPUTEX

    __syncthreads();
    const int erow = lane >> 2, ecol = (lane & 3) * 2;
#pragma unroll
    for (int f = 0; f < 4; ++f) {
        const int n = n0 + wn + f * 16 + erow;
        const float b0 = bih[n] + bhh[n];
        const float b8 = bih[n + 8] + bhh[n + 8];
#pragma unroll
        for (int q = 0; q < 8; ++q) {
            const int m = m0 + wm + q * 8 + ecol;
            *(float2*)(g_xg + (size_t)n * MTOT + m) =
                make_float2(acc[f][q][0] + b0, acc[f][q][1] + b0);
            *(float2*)(g_xg + (size_t)(n + 8) * MTOT + m) =
                make_float2(acc[f][q][2] + b8, acc[f][q][3] + b8);
        }
    }
}

// =====================================================================
// init: reset barrier + convert h0 -> g_hf buf 0 (fp16)
// =====================================================================
__global__ void init_kernel(const float* __restrict__ h0) {
    if (blockIdx.x == 0 && threadIdx.x == 0) g_ctr = 0u;
    const int idx = blockIdx.x * 256 + threadIdx.x;
    const int b = idx >> 10, j = idx & 1023;
    g_hf[(size_t)b * 1024 + j] = __float2half_rn(h0[(size_t)b * HDIM + j]);
}

// =====================================================================
// Kernel 2: recurrent. Single-product fp16 W, h fp16, KC=128, 3 stages,
// split grid barrier (arrive -> prefetch next-step operands -> wait)
// smem: Whi 66048 | Ht 3x17408 | Gs 8448 | Cs 2048 | Rs 32
// =====================================================================
#define GC 128
#define WST    1032
#define WHI_O  0
#define HT_O   66048
#define HSTG   17408
#define GS_O   (HT_O + 3 * HSTG)     // 118272
#define CS_O   (GS_O + 8448)
#define RS_O   (CS_O + 2048)
#define RSMEM  (RS_O + 32)
#define GPAD   66

__global__ void __launch_bounds__(256, 1) recurrent_kernel(
    const float* __restrict__ h0raw, const float* __restrict__ c0,
    const float* __restrict__ whh, const float* __restrict__ retr,
    float* __restrict__ out)
{
    extern __shared__ char s[];
    const unsigned sb = smem_u32(s);
    float* Gs = (float*)(s + GS_O);
    float* Cs = (float*)(s + CS_O);
    float* Rs = (float*)(s + RS_O);

    const int tid = threadIdx.x, lane = tid & 31, wid = tid >> 5;
    const int j0 = blockIdx.x * 8;

    // stage W slice as single fp16 plane
    for (int idx = tid; idx < 32 * 256; idx += 256) {
        const int r = idx >> 8, kq = (idx & 255) << 2;
        const int g = r >> 3, u = r & 7;
        const float4 v = *(const float4*)(whh + (size_t)(g * HDIM + j0 + u) * HDIM + kq);
        __half hi[4];
        hi[0] = __float2half_rn(v.x); hi[1] = __float2half_rn(v.y);
        hi[2] = __float2half_rn(v.z); hi[3] = __float2half_rn(v.w);
        *(uint2*)(s + WHI_O + (r * WST + kq) * 2) = *(uint2*)hi;
    }
    if (tid < 8) Rs[tid] = retr[j0 + tid];
    for (int idx = tid; idx < 512; idx += 256) {
        const int u = idx & 7, b = idx >> 3;
        Cs[u * 64 + b] = c0[(size_t)b * HDIM + j0 + u];
    }
    __syncthreads();

    const int mtile = wid & 1;
    const int npair = wid >> 1;
    const unsigned offA =
        (unsigned)(((mtile * 16 + (lane & 15)) * WST + ((lane >> 4) << 3)) * 2);
    const unsigned offB =
        (unsigned)((npair * 16 + (lane & 7) + ((lane >> 4) << 3)) * 272 +
                   ((((lane >> 3) & 1) << 3) * 2));

    const int u0 = tid & 7,          b0 = tid >> 3;
    const int u1 = (tid + 256) & 7,  b1 = (tid + 256) >> 3;

    float* hT_out = out + (size_t)T_STEPS * BATCH * HDIM;
    float* cT_out = hT_out + (size_t)BATCH * HDIM;

    // preload step-0 epilogue operands
    float xgr[8], hpr[2];
#pragma unroll
    for (int g = 0; g < 4; ++g) {
        xgr[g]     = __ldg(g_xg + (size_t)(g * HDIM + j0 + u0) * MTOT + b0);
        xgr[4 + g] = __ldg(g_xg + (size_t)(g * HDIM + j0 + u1) * MTOT + b1);
    }
    hpr[0] = __ldg(h0raw + (size_t)b0 * HDIM + j0 + u0);
    hpr[1] = __ldg(h0raw + (size_t)b1 * HDIM + j0 + u1);

    for (int t = 0; t < T_STEPS; ++t) {
        const char* hsrc = (const char*)g_hf + (size_t)(t & 1) * 131072;

#define ISSUER(C)                                                            \
        {   const unsigned dstb = sb + HT_O + ((C) % 3) * HSTG;              \
            _Pragma("unroll")                                                \
            for (int i = 0; i < 4; ++i) {                                    \
                const int u = tid + i * 256;                                 \
                const int row = u >> 4, cg = u & 15;                         \
                cp16(dstb + row * 272 + cg * 16,                             \
                     hsrc + (size_t)row * 2048 + (C) * 256 + cg * 16);       \
            }                                                                \
            asm volatile("cp.async.commit_group;" ::: "memory");             \
        }

        ISSUER(0); ISSUER(1);

        float acc0[4] = {0.f, 0.f, 0.f, 0.f};
        float acc1[4] = {0.f, 0.f, 0.f, 0.f};

        for (int c = 0; c < 8; ++c) {
            if (c < 7)
                asm volatile("cp.async.wait_group 1;" ::: "memory");
            else
                asm volatile("cp.async.wait_group 0;" ::: "memory");
            __syncthreads();
            if (c + 2 < 8) ISSUER(c + 2);

            const unsigned stb = sb + HT_O + (c % 3) * HSTG;
#pragma unroll
            for (int ks = 0; ks < 8; ++ks) {
                const unsigned ka = (unsigned)((c * 128 + ks * 16) * 2);
                unsigned ah0, ah1, ah2, ah3;
                unsigned bh0, bh1, bh2, bh3;
                LDM4(ah0, ah1, ah2, ah3, sb + WHI_O + offA + ka);
                LDM4(bh0, bh1, bh2, bh3, stb + offB + ks * 32);
                MMA_F16(acc0, ah0, ah1, ah2, ah3, bh0, bh1);
                MMA_F16(acc1, ah0, ah1, ah2, ah3, bh2, bh3);
            }
        }
#undef ISSUER

        {
            const int row = mtile * 16 + (lane >> 2);
            const int col = npair * 16 + (lane & 3) * 2;
            Gs[row * GPAD + col]           = acc0[0];
            Gs[row * GPAD + col + 1]       = acc0[1];
            Gs[(row + 8) * GPAD + col]     = acc0[2];
            Gs[(row + 8) * GPAD + col + 1] = acc0[3];
            Gs[row * GPAD + col + 8]       = acc1[0];
            Gs[row * GPAD + col + 9]       = acc1[1];
            Gs[(row + 8) * GPAD + col + 8] = acc1[2];
            Gs[(row + 8) * GPAD + col + 9] = acc1[3];
        }
        __syncthreads();

        // epilogue (uses preloaded xgr/hpr)
        float* o_t = out + (size_t)t * BATCH * HDIM;
        __half* hw = g_hf + (size_t)((t + 1) & 1) * 65536;
        float hy0, hy1;
#pragma unroll
        for (int c2 = 0; c2 < 2; ++c2) {
            const int u = c2 ? u1 : u0, b = c2 ? b1 : b0;
            const int j = j0 + u;

            const float gi = Gs[(0 * 8 + u) * GPAD + b] + xgr[c2 * 4 + 0];
            const float gf = Gs[(1 * 8 + u) * GPAD + b] + xgr[c2 * 4 + 1];
            const float gg = Gs[(2 * 8 + u) * GPAD + b] + xgr[c2 * 4 + 2];
            const float go = Gs[(3 * 8 + u) * GPAD + b] + xgr[c2 * 4 + 3];

            const float c = Cs[u * 64 + b];
            const float cy = sigf(gf) * c + sigf(gi) * tanhf(gg);
            float hy = sigf(go) * tanhf(cy);
            const float rv = Rs[u];
            hy = rv * hpr[c2] + (1.f - rv) * hy;

            Cs[u * 64 + b] = cy;
            o_t[(size_t)b * HDIM + j] = hy;
            hw[(size_t)b * 1024 + j] = __float2half_rn(hy);
            if (c2) hy1 = hy; else hy0 = hy;
            if (t == T_STEPS - 1) {
                hT_out[(size_t)b * HDIM + j] = hy;
                cT_out[(size_t)b * HDIM + j] = cy;
            }
        }

        // split barrier: arrive, prefetch next-step operands, then wait
        __threadfence();
        __syncthreads();
        if (tid == 0) atomicAdd(&g_ctr, 1u);

        if (t + 1 < T_STEPS) {
            const size_t m0n = (size_t)(t + 1) * BATCH + b0;
            const size_t m1n = (size_t)(t + 1) * BATCH + b1;
#pragma unroll
            for (int g = 0; g < 4; ++g) {
                xgr[g]     = __ldg(g_xg + (size_t)(g * HDIM + j0 + u0) * MTOT + m0n);
                xgr[4 + g] = __ldg(g_xg + (size_t)(g * HDIM + j0 + u1) * MTOT + m1n);
            }
            // h_prev for next step = this step's hy (local, no reload)
            hpr[0] = hy0;
            hpr[1] = hy1;
        }

        if (tid == 0) {
            const unsigned target = (unsigned)(t + 1) * GC;
            while (*(volatile unsigned*)&g_ctr < target) { }
        }
        __syncthreads();
    }
}

// =====================================================================
extern "C" void kernel_launch(void* const* d_in, const int* in_sizes, int n_in,
                              void* d_out, int out_size)
{
    const float* input_ = (const float*)d_in[0];
    const float* h0     = (const float*)d_in[1];
    const float* c0     = (const float*)d_in[2];
    const float* wih    = (const float*)d_in[3];
    const float* whh    = (const float*)d_in[4];
    const float* bih    = (const float*)d_in[5];
    const float* bhh    = (const float*)d_in[6];
    const float* retr   = (const float*)d_in[7];
    float* out = (float*)d_out;
    (void)in_sizes; (void)n_in; (void)out_size;

    cudaFuncSetAttribute(xgates_mma_kernel,
                         cudaFuncAttributeMaxDynamicSharedMemorySize, XSMEM);
    cudaFuncSetAttribute(recurrent_kernel,
                         cudaFuncAttributeMaxDynamicSharedMemorySize, RSMEM);

    conv_kernel<<<23040, 256>>>(wih, input_);
    xgates_mma_kernel<<<dim3(256, 32), 128, XSMEM>>>(bih, bhh);
    init_kernel<<<256, 256>>>(h0);
    recurrent_kernel<<<GC, 256, RSMEM>>>(h0, c0, whh, retr, out);
}